// round 15
// baseline (speedup 1.0000x reference)
#include <cuda_runtime.h>
#include <cuda_bf16.h>
#include <math.h>
#include <stdint.h>

#define Bc   64
#define Pc   100
#define Nc   1000
#define EMBc 128

// ---- scratch (__device__ globals; no allocation allowed) ----
__device__ __align__(16) float g_K[Bc * Nc * EMBc];
__device__ __align__(16) float g_V[Bc * Nc * EMBc];
__device__ __align__(16) float g_Q[Bc * Pc * EMBc];
__device__ __align__(16) float g_MH[Bc * Pc * EMBc];
__device__ __align__(16) unsigned g_bits[Bc * Pc * 32];
__device__ __align__(16) float g_part[2 * 512 * Pc * 17];
// W in mma.sync B-fragment order: [mat][n(128)][kk(8)][q(4)] x uint4{b0h,b1h,b0l,b1l}
__device__ __align__(16) uint4 g_Wfrag[2 * 128 * 8 * 4];
// Wq frags: [n(128)][kk(9)][q(4)] (k padded 130 -> 144)
__device__ __align__(16) uint4 g_Wqfrag[128 * 9 * 4];

constexpr double X218   = 3.814697265625e-06;
constexpr float  A_COEF = (float)(1.0 / (1.0 + X218));
constexpr float  B_COEF = (float)(1.0 - 1.0 / (1.0 + X218));
constexpr float  INV_SQRT_EMB = 0.08838834764831845f;
constexpr float  LOG2E = 1.44269504088896340736f;

// ---- packed fp32x2 helpers ----
typedef unsigned long long u64t;
__device__ __forceinline__ u64t fma2(u64t a, u64t b, u64t c) {
    u64t d; asm("fma.rn.f32x2 %0, %1, %2, %3;" : "=l"(d) : "l"(a), "l"(b), "l"(c)); return d;
}
__device__ __forceinline__ u64t splat2(float x) {
    u64t d; asm("mov.b64 %0, {%1, %1};" : "=l"(d) : "f"(x)); return d;
}
__device__ __forceinline__ float2 unpack2(u64t v) {
    float2 r; asm("mov.b64 {%0, %1}, %2;" : "=f"(r.x), "=f"(r.y) : "l"(v)); return r;
}
__device__ __forceinline__ float ex2f(float x) {
    float r; asm("ex2.approx.f32 %0, %1;" : "=f"(r) : "f"(x)); return r;
}
__device__ __forceinline__ float rcpf(float x) {
    float r; asm("rcp.approx.f32 %0, %1;" : "=f"(r) : "f"(x)); return r;
}
__device__ __forceinline__ float tanh_scaled(float x, float scale) {
    float t = ex2f(x * (2.f * LOG2E));
    float num = t - 1.f, den = t + 1.f;
    float r = rcpf(den);
    r = r * (2.f - den * r);
    return num * r * scale;
}

// ---- cp.async ----
__device__ __forceinline__ void cp16(void* dst, const void* src) {
    unsigned d = (unsigned)__cvta_generic_to_shared(dst);
    asm volatile("cp.async.cg.shared.global [%0], [%1], 16;" :: "r"(d), "l"(src));
}
#define CP_COMMIT() asm volatile("cp.async.commit_group;" ::: "memory")

// ---- bf16 split helpers ----
__device__ __forceinline__ unsigned packbf2(float a, float b) {
    __nv_bfloat162 v = __floats2bfloat162_rn(a, b);
    return *reinterpret_cast<unsigned*>(&v);
}
__device__ __forceinline__ float bfrt(float x) {
    return __bfloat162float(__float2bfloat16(x));
}
__device__ __forceinline__ unsigned hipack(float a, float b) {
    unsigned r;
    asm("prmt.b32 %0, %1, %2, 0x7632;" : "=r"(r)
        : "r"(__float_as_uint(a)), "r"(__float_as_uint(b)));
    return r;
}
__device__ __forceinline__ float hif(float x) {
    return __uint_as_float(__float_as_uint(x) & 0xFFFF0000u);
}

// ---- mma.sync m16n8k16 bf16, fp32 accum ----
__device__ __forceinline__ void mma16816(float& d0, float& d1, float& d2, float& d3,
                                         unsigned a0, unsigned a1, unsigned a2, unsigned a3,
                                         unsigned b0, unsigned b1) {
    asm volatile(
        "mma.sync.aligned.m16n8k16.row.col.f32.bf16.bf16.f32 "
        "{%0,%1,%2,%3}, {%4,%5,%6,%7}, {%8,%9}, {%0,%1,%2,%3};"
        : "+f"(d0), "+f"(d1), "+f"(d2), "+f"(d3)
        : "r"(a0), "r"(a1), "r"(a2), "r"(a3), "r"(b0), "r"(b1));
}

// ============================================================================
// Kernel 0: pack ninf mask into bits (1 = masked).
// ============================================================================
__global__ void bits_kernel(const float* __restrict__ ninf) {
    const int w = blockIdx.x * 8 + (threadIdx.x >> 5);
    if (w >= Bc * Pc * 32) return;
    const int lane = threadIdx.x & 31;
    const int row = w >> 5, word = w & 31;
    const int n = word * 32 + lane;
    float v = -1.f;
    if (n < 1000) v = ninf[row * 1000 + n];
    unsigned m = __ballot_sync(0xffffffffu, v < -0.5f);
    if (lane == 0) g_bits[w] = m;
}

// ============================================================================
// Kernel 0b: pack Wk/Wv (8192) + Wq (4608) into B-fragment order, hi/lo split.
// ============================================================================
__global__ void wprep_kernel(const float* __restrict__ Wk, const float* __restrict__ Wv,
                             const float* __restrict__ Wq) {
    int idx = blockIdx.x * 256 + threadIdx.x;   // 12800 total
    if (idx < 8192) {
        const int mat = idx >> 12;
        const int n   = (idx >> 5) & 127;
        const int kk  = (idx >> 2) & 7;
        const int q   = idx & 3;
        const int k   = kk * 16 + q * 2;
        const float* W = mat ? Wv : Wk;
        float w0 = W[k * 128 + n],       w1 = W[(k + 1) * 128 + n];
        float w2 = W[(k + 8) * 128 + n], w3 = W[(k + 9) * 128 + n];
        uint4 v;
        v.x = packbf2(w0, w1);
        v.y = packbf2(w2, w3);
        v.z = packbf2(w0 - bfrt(w0), w1 - bfrt(w1));
        v.w = packbf2(w2 - bfrt(w2), w3 - bfrt(w3));
        g_Wfrag[idx] = v;
    } else if (idx < 12800) {
        const int j  = idx - 8192;
        const int n  = j / 36;
        const int rm = j % 36;
        const int kk = rm >> 2;
        const int q  = rm & 3;
        const int k  = kk * 16 + q * 2;
        float w0 = (k     < 130) ? Wq[(k)     * 128 + n] : 0.f;
        float w1 = (k + 1 < 130) ? Wq[(k + 1) * 128 + n] : 0.f;
        float w2 = (k + 8 < 130) ? Wq[(k + 8) * 128 + n] : 0.f;
        float w3 = (k + 9 < 130) ? Wq[(k + 9) * 128 + n] : 0.f;
        uint4 v;
        v.x = packbf2(w0, w1);
        v.y = packbf2(w2, w3);
        v.z = packbf2(w0 - bfrt(w0), w1 - bfrt(w1));
        v.w = packbf2(w2 - bfrt(w2), w3 - bfrt(w3));
        g_Wqfrag[j] = v;
    }
}

// ============================================================================
// Kernel 1: K AND V = E @ {Wk,Wv} in one block. E packed once cooperatively
// into fragment-ordered hi/lo smem (hi in AB[0..2047], lo in AB[2048..4095]);
// warp = 16-row tile x 128 cols; inner loop 1 LDS.128 + LDG Wfrag + 3 MMA.
// ============================================================================
__global__ void __launch_bounds__(256, 2)
kv_mma_kernel(const float* __restrict__ E) {
    extern __shared__ __align__(16) uint4 AB[];   // 4096 x 16B = 64KB
    const int tid  = threadIdx.x;
    const int wid  = tid >> 5;
    const int lane = tid & 31;
    const int R0   = blockIdx.x * 128;
    const int rfrag = lane >> 2;
    const int qq    = lane & 3;
    const int c2    = qq * 2;

    // cooperative pack: 2048 cells (tile, kk, rfrag, q), each -> hi + lo uint4
    for (int l = tid; l < 2048; l += 256) {
        const int tile = l >> 8;
        const int kk   = (l >> 5) & 7;
        const int rf   = (l >> 2) & 7;
        const int q    = l & 3;
        const int r0 = R0 + tile * 16 + rf;
        const int k0 = kk * 16 + q * 2;
        float2 a0 = *(const float2*)(E + (size_t)r0 * 128 + k0);
        float2 a1 = *(const float2*)(E + (size_t)(r0 + 8) * 128 + k0);
        float2 a2 = *(const float2*)(E + (size_t)r0 * 128 + k0 + 8);
        float2 a3 = *(const float2*)(E + (size_t)(r0 + 8) * 128 + k0 + 8);
        AB[l] = make_uint4(hipack(a0.x, a0.y), hipack(a1.x, a1.y),
                           hipack(a2.x, a2.y), hipack(a3.x, a3.y));
        AB[2048 + l] = make_uint4(
            packbf2(a0.x - hif(a0.x), a0.y - hif(a0.y)),
            packbf2(a1.x - hif(a1.x), a1.y - hif(a1.y)),
            packbf2(a2.x - hif(a2.x), a2.y - hif(a2.y)),
            packbf2(a3.x - hif(a3.x), a3.y - hif(a3.y)));
    }
    __syncthreads();

    #pragma unroll
    for (int mat = 0; mat < 2; ++mat) {
        const uint4* Wf = g_Wfrag + mat * 4096;
        float acc[16][4];
        #pragma unroll
        for (int nt = 0; nt < 16; ++nt)
            #pragma unroll
            for (int i = 0; i < 4; ++i) acc[nt][i] = 0.f;

        #pragma unroll
        for (int kk = 0; kk < 8; ++kk) {
            const int cell = (wid * 8 + kk) * 32 + lane;
            uint4 hi = AB[cell];
            uint4 lo = AB[2048 + cell];
            #pragma unroll
            for (int nt = 0; nt < 16; ++nt) {
                const int n = nt * 8 + rfrag;
                uint4 bf = Wf[(n * 8 + kk) * 4 + qq];
                mma16816(acc[nt][0], acc[nt][1], acc[nt][2], acc[nt][3],
                         hi.x, hi.y, hi.z, hi.w, bf.x, bf.y);
                mma16816(acc[nt][0], acc[nt][1], acc[nt][2], acc[nt][3],
                         lo.x, lo.y, lo.z, lo.w, bf.x, bf.y);
                mma16816(acc[nt][0], acc[nt][1], acc[nt][2], acc[nt][3],
                         hi.x, hi.y, hi.z, hi.w, bf.z, bf.w);
            }
        }

        float* dst = (mat ? g_V : g_K);
        const int row = R0 + wid * 16 + rfrag;
        #pragma unroll
        for (int nt = 0; nt < 16; ++nt) {
            const int col = nt * 8 + c2;
            *(float2*)(dst + (size_t)row * 128 + col)       = make_float2(acc[nt][0], acc[nt][1]);
            *(float2*)(dst + (size_t)(row + 8) * 128 + col) = make_float2(acc[nt][2], acc[nt][3]);
        }
    }
}

// ============================================================================
// Kernel 2: Q = concat(eln, load, time) @ Wq via mma.sync, 64-row tiles
// (validated round 12).
// ============================================================================
__global__ void __launch_bounds__(256)
q_mma_kernel(const float* __restrict__ eln,
             const float* __restrict__ loadv,
             const float* __restrict__ timev) {
    __shared__ __align__(16) float As[64][148];
    const int tid  = threadIdx.x;
    const int wid  = tid >> 5;
    const int lane = tid & 31;
    const int R0   = blockIdx.x * 64;
    const int wr   = wid >> 1;
    const int wc   = wid & 1;

    for (int l = tid; l < 2048; l += 256) {
        int row = l >> 5, q = l & 31;
        cp16(&As[row][q * 4], eln + (size_t)(R0 + row) * 128 + q * 4);
    }
    CP_COMMIT();
    for (int l = tid; l < 64 * 5; l += 256) {
        int row = l / 5, cq = (l % 5) * 4 + 128;
        float4 v = make_float4(0.f, 0.f, 0.f, 0.f);
        if (cq == 128) { v.x = loadv[R0 + row]; v.y = timev[R0 + row]; }
        *(float4*)&As[row][cq] = v;
    }

    float acc[8][4];
    #pragma unroll
    for (int nt = 0; nt < 8; ++nt)
        #pragma unroll
        for (int i = 0; i < 4; ++i) acc[nt][i] = 0.f;

    const int rfrag = lane >> 2;
    const int cfrag = (lane & 3) * 2;

    asm volatile("cp.async.wait_group 0;" ::: "memory");
    __syncthreads();

    #pragma unroll
    for (int kk = 0; kk < 9; ++kk) {
        unsigned ahi[4], alo[4];
        {
            const float* r0p = &As[wr * 16 + rfrag][kk * 16 + cfrag];
            const float* r8p = r0p + 8 * 148;
            float2 x0 = *(const float2*)r0p;
            float2 x1 = *(const float2*)r8p;
            float2 x2 = *(const float2*)(r0p + 8);
            float2 x3 = *(const float2*)(r8p + 8);
            ahi[0] = hipack(x0.x, x0.y);
            ahi[1] = hipack(x1.x, x1.y);
            ahi[2] = hipack(x2.x, x2.y);
            ahi[3] = hipack(x3.x, x3.y);
            alo[0] = packbf2(x0.x - hif(x0.x), x0.y - hif(x0.y));
            alo[1] = packbf2(x1.x - hif(x1.x), x1.y - hif(x1.y));
            alo[2] = packbf2(x2.x - hif(x2.x), x2.y - hif(x2.y));
            alo[3] = packbf2(x3.x - hif(x3.x), x3.y - hif(x3.y));
        }
        #pragma unroll
        for (int nt = 0; nt < 8; ++nt) {
            const int n = wc * 64 + nt * 8 + rfrag;
            uint4 bf = g_Wqfrag[(n * 9 + kk) * 4 + (lane & 3)];
            mma16816(acc[nt][0], acc[nt][1], acc[nt][2], acc[nt][3],
                     ahi[0], ahi[1], ahi[2], ahi[3], bf.x, bf.y);
            mma16816(acc[nt][0], acc[nt][1], acc[nt][2], acc[nt][3],
                     alo[0], alo[1], alo[2], alo[3], bf.x, bf.y);
            mma16816(acc[nt][0], acc[nt][1], acc[nt][2], acc[nt][3],
                     ahi[0], ahi[1], ahi[2], ahi[3], bf.z, bf.w);
        }
    }

    const int row = R0 + wr * 16 + rfrag;
    #pragma unroll
    for (int nt = 0; nt < 8; ++nt) {
        const int col = wc * 64 + nt * 8 + cfrag;
        *(float2*)(g_Q + (size_t)row * 128 + col)       = make_float2(acc[nt][0], acc[nt][1]);
        *(float2*)(g_Q + (size_t)(row + 8) * 128 + col) = make_float2(acc[nt][2], acc[nt][3]);
    }
}

// ============================================================================
// Kernel 3: attention via mma.sync, 2 splits of 512 n (8 tiles of 64).
// Shared fragment pre-packing (validated round 13).
// ============================================================================
__global__ void __launch_bounds__(224, 4)
attn_kernel() {
    const int bh    = blockIdx.x;
    const int split = blockIdx.y;
    const int b     = bh >> 3;
    const int h     = bh & 7;
    const int tid   = threadIdx.x;
    const int wid   = tid >> 5;
    const int lane  = tid & 31;
    const int rfrag = lane >> 2;
    const int c2    = (lane & 3) * 2;
    const int nbeg  = split * 512;

    __shared__ __align__(16) float Ks[2][64][16];
    __shared__ __align__(16) float Vs[2][64][16];
    __shared__ __align__(16) uint4 KB[2][64][4];
    __shared__ __align__(16) uint4 VB[2][256];

    const float* Kbase = g_K + b * 1000 * 128 + h * 16;
    const float* Vbase = g_V + b * 1000 * 128 + h * 16;

    for (int l = tid; l < 256; l += 224) {
        int j = l >> 2, qd = (l & 3) * 4;
        int n = nbeg + j; if (n > 999) n = 999;
        cp16(&Ks[0][j][qd], Kbase + n * 128 + qd);
        cp16(&Vs[0][j][qd], Vbase + n * 128 + qd);
    }
    CP_COMMIT();

    const int p0  = wid * 16 + rfrag;
    const int p1  = p0 + 8;
    const int pr0 = p0 < 100 ? p0 : 99;
    const int pr1 = p1 < 100 ? p1 : 99;
    unsigned qhi[4], qlo[4];
    {
        const float qs = 0.25f * LOG2E;
        const float* q0p = g_Q + (b * 100 + pr0) * 128 + h * 16;
        const float* q1p = g_Q + (b * 100 + pr1) * 128 + h * 16;
        float2 x0 = *(const float2*)(q0p + c2);
        float2 x1 = *(const float2*)(q1p + c2);
        float2 x2 = *(const float2*)(q0p + c2 + 8);
        float2 x3 = *(const float2*)(q1p + c2 + 8);
        float v0 = x0.x * qs, v1 = x0.y * qs, v2 = x1.x * qs, v3 = x1.y * qs;
        float v4 = x2.x * qs, v5 = x2.y * qs, v6 = x3.x * qs, v7 = x3.y * qs;
        qhi[0] = hipack(v0, v1); qhi[1] = hipack(v2, v3);
        qhi[2] = hipack(v4, v5); qhi[3] = hipack(v6, v7);
        qlo[0] = packbf2(v0 - hif(v0), v1 - hif(v1));
        qlo[1] = packbf2(v2 - hif(v2), v3 - hif(v3));
        qlo[2] = packbf2(v4 - hif(v4), v5 - hif(v5));
        qlo[3] = packbf2(v6 - hif(v6), v7 - hif(v7));
    }
    const unsigned* bw0 = g_bits + (b * 100 + pr0) * 32;
    const unsigned* bw1 = g_bits + (b * 100 + pr1) * 32;

    float acc[2][4];
    #pragma unroll
    for (int dt = 0; dt < 2; ++dt)
        #pragma unroll
        for (int i = 0; i < 4; ++i) acc[dt][i] = 0.f;
    float ls0 = 0.f, ls1 = 0.f;

    for (int t = 0; t < 8; ++t) {
        const int s    = t & 1;
        const int base = nbeg + t * 64;

        asm volatile("cp.async.wait_group 0;" ::: "memory");
        __syncthreads();

        for (int l = tid; l < 256; l += 224) {
            int row = l >> 2, q = l & 3;
            float2 a  = *(const float2*)&Ks[s][row][2 * q];
            float2 b2 = *(const float2*)&Ks[s][row][2 * q + 8];
            KB[s][row][q] = make_uint4(
                hipack(a.x, a.y), hipack(b2.x, b2.y),
                packbf2(a.x - hif(a.x), a.y - hif(a.y)),
                packbf2(b2.x - hif(b2.x), b2.y - hif(b2.y)));
        }
        for (int l = tid; l < 256; l += 224) {
            int kc = l >> 6, qq2 = (l >> 4) & 3, d = l & 15;
            int r0 = kc * 16 + 2 * qq2;
            float v0 = Vs[s][r0][d],     v1 = Vs[s][r0 + 1][d];
            float v2 = Vs[s][r0 + 8][d], v3 = Vs[s][r0 + 9][d];
            VB[s][l] = make_uint4(
                hipack(v0, v1), hipack(v2, v3),
                packbf2(v0 - hif(v0), v1 - hif(v1)),
                packbf2(v2 - hif(v2), v3 - hif(v3)));
        }

        if (t + 1 < 8) {
            const int ns = 1 - s, nb2 = base + 64;
            for (int l = tid; l < 256; l += 224) {
                int j = l >> 2, qd = (l & 3) * 4;
                int n = nb2 + j; if (n > 999) n = 999;
                cp16(&Ks[ns][j][qd], Kbase + n * 128 + qd);
                cp16(&Vs[ns][j][qd], Vbase + n * 128 + qd);
            }
            CP_COMMIT();
        }
        __syncthreads();

        const unsigned mw0a = bw0[base >> 5], mw0b = bw0[(base >> 5) + 1];
        const unsigned mw1a = bw1[base >> 5], mw1b = bw1[(base >> 5) + 1];

        #pragma unroll
        for (int kc = 0; kc < 4; ++kc) {
            unsigned phi[4], plo[4];
            #pragma unroll
            for (int jj = 0; jj < 2; ++jj) {
                const int j    = kc * 2 + jj;
                const int trow = j * 8 + rfrag;
                uint4 kf = KB[s][trow][lane & 3];
                float d0 = 0.f, d1 = 0.f, d2 = 0.f, d3 = 0.f;
                mma16816(d0, d1, d2, d3, qhi[0], qhi[1], qhi[2], qhi[3], kf.x, kf.y);
                mma16816(d0, d1, d2, d3, qlo[0], qlo[1], qlo[2], qlo[3], kf.x, kf.y);
                mma16816(d0, d1, d2, d3, qhi[0], qhi[1], qhi[2], qhi[3], kf.z, kf.w);

                const int nsel = j * 8 + c2;
                const int gn   = base + nsel;
                const unsigned w0 = (nsel < 32) ? mw0a : mw0b;
                const unsigned w1 = (nsel < 32) ? mw1a : mw1b;
                const int bit = nsel & 31;
                float e0 = ex2f(d0), e1 = ex2f(d1), e2 = ex2f(d2), e3 = ex2f(d3);
                if (((w0 >> bit) & 1u)       || gn >= 1000)     e0 = 0.f;
                if (((w0 >> (bit + 1)) & 1u) || gn + 1 >= 1000) e1 = 0.f;
                if (((w1 >> bit) & 1u)       || gn >= 1000)     e2 = 0.f;
                if (((w1 >> (bit + 1)) & 1u) || gn + 1 >= 1000) e3 = 0.f;
                ls0 += e0 + e1;
                ls1 += e2 + e3;
                phi[2 * jj]     = packbf2(e0, e1);
                phi[2 * jj + 1] = packbf2(e2, e3);
                plo[2 * jj]     = packbf2(e0 - bfrt(e0), e1 - bfrt(e1));
                plo[2 * jj + 1] = packbf2(e2 - bfrt(e2), e3 - bfrt(e3));
            }
            #pragma unroll
            for (int dt = 0; dt < 2; ++dt) {
                uint4 vf = VB[s][kc * 64 + (lane & 3) * 16 + dt * 8 + rfrag];
                mma16816(acc[dt][0], acc[dt][1], acc[dt][2], acc[dt][3],
                         phi[0], phi[1], phi[2], phi[3], vf.x, vf.y);
                mma16816(acc[dt][0], acc[dt][1], acc[dt][2], acc[dt][3],
                         plo[0], plo[1], plo[2], plo[3], vf.x, vf.y);
                mma16816(acc[dt][0], acc[dt][1], acc[dt][2], acc[dt][3],
                         phi[0], phi[1], phi[2], phi[3], vf.z, vf.w);
            }
        }
    }

    ls0 += __shfl_xor_sync(0xffffffffu, ls0, 1);
    ls0 += __shfl_xor_sync(0xffffffffu, ls0, 2);
    ls1 += __shfl_xor_sync(0xffffffffu, ls1, 1);
    ls1 += __shfl_xor_sync(0xffffffffu, ls1, 2);

    if (p0 < 100) {
        float* pp = g_part + ((split * 512 + bh) * 100 + p0) * 17;
        pp[c2]     = acc[0][0]; pp[c2 + 1]     = acc[0][1];
        pp[8 + c2] = acc[1][0]; pp[8 + c2 + 1] = acc[1][1];
        if ((lane & 3) == 0) pp[16] = ls0;
    }
    if (p1 < 100) {
        float* pp = g_part + ((split * 512 + bh) * 100 + p1) * 17;
        pp[c2]     = acc[0][2]; pp[c2 + 1]     = acc[0][3];
        pp[8 + c2] = acc[1][2]; pp[8 + c2 + 1] = acc[1][3];
        if ((lane & 3) == 0) pp[16] = ls1;
    }
}

// ============================================================================
// Kernel 4: fused combine (2 splits) + MH = (normalized O) @ Wc + bc
// ============================================================================
__global__ void __launch_bounds__(256)
mh_kernel(const float* __restrict__ Wc, const float* __restrict__ bc) {
    __shared__ float As[128][20];
    __shared__ float sinv[16][8];
    const int tid = threadIdx.x;
    const int R0  = blockIdx.x * 16;
    const int tx  = tid & 63;
    const int ty  = tid >> 6;

    if (tid < 128) {
        int row = tid >> 3, h = tid & 7;
        int gr = R0 + row;
        int b = gr / 100, p = gr % 100;
        int bh = b * 8 + h;
        float ls = 0.f;
        #pragma unroll
        for (int sp = 0; sp < 2; ++sp)
            ls += g_part[((sp * 512 + bh) * 100 + p) * 17 + 16];
        sinv[row][h] = 1.f / ls;
    }
    __syncthreads();

    for (int l = tid; l < 2048; l += 256) {
        int row = l >> 7, col = l & 127;
        int gr = R0 + row;
        int b = gr / 100, p = gr % 100;
        int h = col >> 4, d = col & 15;
        int bh = b * 8 + h;
        float s = 0.f;
        #pragma unroll
        for (int sp = 0; sp < 2; ++sp)
            s += g_part[((sp * 512 + bh) * 100 + p) * 17 + d];
        As[col][row] = s * sinv[row][h];
    }
    __syncthreads();

    u64t acc[4];
    {
        float2 bb = *(const float2*)(bc + tx * 2);
        u64t bb2; asm("mov.b64 %0, {%1, %2};" : "=l"(bb2) : "f"(bb.x), "f"(bb.y));
        acc[0] = bb2; acc[1] = bb2; acc[2] = bb2; acc[3] = bb2;
    }

    #pragma unroll 8
    for (int k = 0; k < 128; ++k) {
        u64t w = *(const u64t*)(Wc + k * 128 + tx * 2);
        float4 a = *(const float4*)&As[k][ty * 4];
        acc[0] = fma2(splat2(a.x), w, acc[0]);
        acc[1] = fma2(splat2(a.y), w, acc[1]);
        acc[2] = fma2(splat2(a.z), w, acc[2]);
        acc[3] = fma2(splat2(a.w), w, acc[3]);
    }

    #pragma unroll
    for (int r = 0; r < 4; ++r)
        *(u64t*)(g_MH + (R0 + ty * 4 + r) * 128 + tx * 2) = acc[r];
}

// ============================================================================
// Kernel 5: score = MH @ E^T via mma.sync with cooperative E fragment
// pre-packing (validated round 14).
// ============================================================================
__global__ void __launch_bounds__(224, 2)
score_kernel(const float* __restrict__ Enodes,
             const float* __restrict__ cur_dist,
             const float* __restrict__ noise,
             float* __restrict__ out) {
    extern __shared__ __align__(16) uint4 EB[];   // [128][33]
    const int tid   = threadIdx.x;
    const int wid   = tid >> 5;
    const int lane  = tid & 31;
    const int rfrag = lane >> 2;
    const int c2    = (lane & 3) * 2;
    const int n0    = blockIdx.x * 128;
    const int b     = blockIdx.y;

    for (int l = tid; l < 4096; l += 224) {
        const int n  = l >> 5;
        const int j  = l & 31;
        const int k  = (j >> 2) * 16 + (j & 3) * 2;
        int gn = n0 + n; if (gn > 999) gn = 999;
        const float* ep = Enodes + (size_t)(b * 1000 + gn) * 128 + k;
        float2 a  = *(const float2*)ep;
        float2 c  = *(const float2*)(ep + 8);
        EB[n * 33 + j] = make_uint4(
            hipack(a.x, a.y), hipack(c.x, c.y),
            packbf2(a.x - hif(a.x), a.y - hif(a.y)),
            packbf2(c.x - hif(c.x), c.y - hif(c.y)));
    }
    __syncthreads();

    const int p0  = wid * 16 + rfrag;
    const int p1  = p0 + 8;
    const int pr0 = p0 < 100 ? p0 : 99;
    const int pr1 = p1 < 100 ? p1 : 99;
    const float* m0base = g_MH + (size_t)(b * 100 + pr0) * 128;
    const float* m1base = g_MH + (size_t)(b * 100 + pr1) * 128;

    float acc[16][4];
    #pragma unroll
    for (int nt = 0; nt < 16; ++nt)
        #pragma unroll
        for (int i = 0; i < 4; ++i) acc[nt][i] = 0.f;

    #pragma unroll
    for (int kk = 0; kk < 8; ++kk) {
        unsigned ahi[4], alo[4];
        {
            float2 x0 = *(const float2*)(m0base + kk * 16 + c2);
            float2 x1 = *(const float2*)(m1base + kk * 16 + c2);
            float2 x2 = *(const float2*)(m0base + kk * 16 + c2 + 8);
            float2 x3 = *(const float2*)(m1base + kk * 16 + c2 + 8);
            ahi[0] = hipack(x0.x, x0.y); ahi[1] = hipack(x1.x, x1.y);
            ahi[2] = hipack(x2.x, x2.y); ahi[3] = hipack(x3.x, x3.y);
            alo[0] = packbf2(x0.x - hif(x0.x), x0.y - hif(x0.y));
            alo[1] = packbf2(x1.x - hif(x1.x), x1.y - hif(x1.y));
            alo[2] = packbf2(x2.x - hif(x2.x), x2.y - hif(x2.y));
            alo[3] = packbf2(x3.x - hif(x3.x), x3.y - hif(x3.y));
        }
        #pragma unroll
        for (int nt = 0; nt < 16; ++nt) {
            uint4 bf = EB[(nt * 8 + rfrag) * 33 + kk * 4 + (lane & 3)];
            mma16816(acc[nt][0], acc[nt][1], acc[nt][2], acc[nt][3],
                     ahi[0], ahi[1], ahi[2], ahi[3], bf.x, bf.y);
            mma16816(acc[nt][0], acc[nt][1], acc[nt][2], acc[nt][3],
                     alo[0], alo[1], alo[2], alo[3], bf.x, bf.y);
            mma16816(acc[nt][0], acc[nt][1], acc[nt][2], acc[nt][3],
                     ahi[0], ahi[1], ahi[2], ahi[3], bf.z, bf.w);
        }
    }

    #pragma unroll
    for (int nt = 0; nt < 16; ++nt) {
        const int cn = n0 + nt * 8 + c2;
        if (cn < 1000) {
            #pragma unroll
            for (int dt = 0; dt < 2; ++dt) {
                const int p = dt ? p1 : p0;
                if (p < 100) {
                    const int idx = (b * 100 + p) * 1000 + cn;
                    float2 cd = *(const float2*)(cur_dist + idx);
                    float2 nz = *(const float2*)(noise + idx);
                    float s0 = acc[nt][dt * 2 + 0];
                    float s1 = acc[nt][dt * 2 + 1];
                    float h0 = -__logf(fmaf(2.f, cd.x, 1e-6f));
                    float h1 = -__logf(fmaf(2.f, cd.y, 1e-6f));
                    float r0 = tanh_scaled(s0 * INV_SQRT_EMB + A_COEF * h0 + B_COEF * nz.x, 10.f);
                    float r1 = tanh_scaled(s1 * INV_SQRT_EMB + A_COEF * h1 + B_COEF * nz.y, 10.f);
                    *(float2*)(out + idx) = make_float2(r0, r1);
                }
            }
        }
    }
}

// ============================================================================
// Kernel 6: masked in-place row softmax, constant shift M=10, float4 path.
// ============================================================================
__global__ void __launch_bounds__(256)
softmax_kernel(float* __restrict__ out) {
    const int row = blockIdx.x;
    const int tid = threadIdx.x;
    float* sp = out + row * 1000;

    __shared__ unsigned sbw[32];
    __shared__ float ssum[8];
    if (tid < 32) sbw[tid] = g_bits[row * 32 + tid];
    __syncthreads();

    float e0 = 0.f, e1 = 0.f, e2 = 0.f, e3 = 0.f, lsum = 0.f;
    if (tid < 250) {
        float4 v = *(const float4*)(sp + tid * 4);
        const unsigned w  = sbw[tid >> 3];
        const int      sh = (tid * 4) & 31;
        e0 = ((w >> sh)       & 1u) ? 0.f : __expf(v.x - 10.f);
        e1 = ((w >> (sh + 1)) & 1u) ? 0.f : __expf(v.y - 10.f);
        e2 = ((w >> (sh + 2)) & 1u) ? 0.f : __expf(v.z - 10.f);
        e3 = ((w >> (sh + 3)) & 1u) ? 0.f : __expf(v.w - 10.f);
        lsum = (e0 + e1) + (e2 + e3);
    }
    #pragma unroll
    for (int o = 16; o; o >>= 1) lsum += __shfl_xor_sync(0xffffffffu, lsum, o);
    if ((tid & 31) == 0) ssum[tid >> 5] = lsum;
    __syncthreads();
    float S = 0.f;
    #pragma unroll
    for (int w = 0; w < 8; ++w) S += ssum[w];

    const float inv = 1.f / S;
    if (tid < 250)
        *(float4*)(sp + tid * 4) = make_float4(e0 * inv, e1 * inv, e2 * inv, e3 * inv);
}

// ============================================================================
extern "C" void kernel_launch(void* const* d_in, const int* in_sizes, int n_in,
                              void* d_out, int out_size) {
    const float* eln      = (const float*)d_in[0];
    const float* loadv    = (const float*)d_in[1];
    const float* timev    = (const float*)d_in[2];
    const float* cur_dist = (const float*)d_in[3];
    const float* ninf     = (const float*)d_in[4];
    const float* noise    = (const float*)d_in[5];
    const float* Enodes   = (const float*)d_in[6];
    const float* Wq       = (const float*)d_in[7];
    const float* Wk       = (const float*)d_in[8];
    const float* Wv       = (const float*)d_in[9];
    const float* Wc       = (const float*)d_in[10];
    const float* bc       = (const float*)d_in[11];
    float* out = (float*)d_out;

    const int KV_SMEM = 4096 * 16;       // 65536 B
    const int SC_SMEM = 128 * 33 * 16;   // 67584 B
    cudaFuncSetAttribute(kv_mma_kernel, cudaFuncAttributeMaxDynamicSharedMemorySize, KV_SMEM);
    cudaFuncSetAttribute(score_kernel,  cudaFuncAttributeMaxDynamicSharedMemorySize, SC_SMEM);

    bits_kernel<<<25600, 256>>>(ninf);
    wprep_kernel<<<50, 256>>>(Wk, Wv, Wq);
    kv_mma_kernel<<<500, 256, KV_SMEM>>>(Enodes);
    q_mma_kernel<<<100, 256>>>(eln, loadv, timev);
    attn_kernel<<<dim3(512, 2), 224>>>();
    mh_kernel<<<400, 256>>>(Wc, bc);
    score_kernel<<<dim3(8, 64), 224, SC_SMEM>>>(Enodes, cur_dist, noise, out);
    softmax_kernel<<<6400, 256>>>(out);
}

// round 16
// speedup vs baseline: 1.1045x; 1.1045x over previous
#include <cuda_runtime.h>
#include <cuda_bf16.h>
#include <math.h>
#include <stdint.h>

#define Bc   64
#define Pc   100
#define Nc   1000
#define EMBc 128

// ---- scratch (__device__ globals; no allocation allowed) ----
__device__ __align__(16) float g_K[Bc * Nc * EMBc];
__device__ __align__(16) float g_V[Bc * Nc * EMBc];
__device__ __align__(16) float g_Q[Bc * Pc * EMBc];
__device__ __align__(16) float g_MH[Bc * Pc * EMBc];
__device__ __align__(16) unsigned g_bits[Bc * Pc * 32];
__device__ __align__(16) float g_part[4 * 512 * Pc * 17];
// W in mma.sync B-fragment order: [mat][n(128)][kk(8)][q(4)] x uint4{b0h,b1h,b0l,b1l}
__device__ __align__(16) uint4 g_Wfrag[2 * 128 * 8 * 4];
// Wq frags: [n(128)][kk(9)][q(4)] (k padded 130 -> 144)
__device__ __align__(16) uint4 g_Wqfrag[128 * 9 * 4];

constexpr double X218   = 3.814697265625e-06;
constexpr float  A_COEF = (float)(1.0 / (1.0 + X218));
constexpr float  B_COEF = (float)(1.0 - 1.0 / (1.0 + X218));
constexpr float  INV_SQRT_EMB = 0.08838834764831845f;
constexpr float  LOG2E = 1.44269504088896340736f;

// ---- packed fp32x2 helpers ----
typedef unsigned long long u64t;
__device__ __forceinline__ u64t fma2(u64t a, u64t b, u64t c) {
    u64t d; asm("fma.rn.f32x2 %0, %1, %2, %3;" : "=l"(d) : "l"(a), "l"(b), "l"(c)); return d;
}
__device__ __forceinline__ u64t splat2(float x) {
    u64t d; asm("mov.b64 %0, {%1, %1};" : "=l"(d) : "f"(x)); return d;
}
__device__ __forceinline__ float2 unpack2(u64t v) {
    float2 r; asm("mov.b64 {%0, %1}, %2;" : "=f"(r.x), "=f"(r.y) : "l"(v)); return r;
}
__device__ __forceinline__ float ex2f(float x) {
    float r; asm("ex2.approx.f32 %0, %1;" : "=f"(r) : "f"(x)); return r;
}
__device__ __forceinline__ float rcpf(float x) {
    float r; asm("rcp.approx.f32 %0, %1;" : "=f"(r) : "f"(x)); return r;
}
__device__ __forceinline__ float tanh_scaled(float x, float scale) {
    float t = ex2f(x * (2.f * LOG2E));
    float num = t - 1.f, den = t + 1.f;
    float r = rcpf(den);
    r = r * (2.f - den * r);
    return num * r * scale;
}

// ---- cp.async ----
__device__ __forceinline__ void cp16(void* dst, const void* src) {
    unsigned d = (unsigned)__cvta_generic_to_shared(dst);
    asm volatile("cp.async.cg.shared.global [%0], [%1], 16;" :: "r"(d), "l"(src));
}
#define CP_COMMIT() asm volatile("cp.async.commit_group;" ::: "memory")

// ---- bf16 split helpers ----
__device__ __forceinline__ unsigned packbf2(float a, float b) {
    __nv_bfloat162 v = __floats2bfloat162_rn(a, b);
    return *reinterpret_cast<unsigned*>(&v);
}
__device__ __forceinline__ float bfrt(float x) {
    return __bfloat162float(__float2bfloat16(x));
}
__device__ __forceinline__ unsigned hipack(float a, float b) {
    unsigned r;
    asm("prmt.b32 %0, %1, %2, 0x7632;" : "=r"(r)
        : "r"(__float_as_uint(a)), "r"(__float_as_uint(b)));
    return r;
}
__device__ __forceinline__ float hif(float x) {
    return __uint_as_float(__float_as_uint(x) & 0xFFFF0000u);
}

// ---- mma.sync m16n8k16 bf16, fp32 accum ----
__device__ __forceinline__ void mma16816(float& d0, float& d1, float& d2, float& d3,
                                         unsigned a0, unsigned a1, unsigned a2, unsigned a3,
                                         unsigned b0, unsigned b1) {
    asm volatile(
        "mma.sync.aligned.m16n8k16.row.col.f32.bf16.bf16.f32 "
        "{%0,%1,%2,%3}, {%4,%5,%6,%7}, {%8,%9}, {%0,%1,%2,%3};"
        : "+f"(d0), "+f"(d1), "+f"(d2), "+f"(d3)
        : "r"(a0), "r"(a1), "r"(a2), "r"(a3), "r"(b0), "r"(b1));
}

// ============================================================================
// Kernel 0: pack ninf mask into bits (1 = masked).
// ============================================================================
__global__ void bits_kernel(const float* __restrict__ ninf) {
    const int w = blockIdx.x * 8 + (threadIdx.x >> 5);
    if (w >= Bc * Pc * 32) return;
    const int lane = threadIdx.x & 31;
    const int row = w >> 5, word = w & 31;
    const int n = word * 32 + lane;
    float v = -1.f;
    if (n < 1000) v = ninf[row * 1000 + n];
    unsigned m = __ballot_sync(0xffffffffu, v < -0.5f);
    if (lane == 0) g_bits[w] = m;
}

// ============================================================================
// Kernel 0b: pack Wk/Wv (8192) + Wq (4608) into B-fragment order, hi/lo split.
// ============================================================================
__global__ void wprep_kernel(const float* __restrict__ Wk, const float* __restrict__ Wv,
                             const float* __restrict__ Wq) {
    int idx = blockIdx.x * 256 + threadIdx.x;   // 12800 total
    if (idx < 8192) {
        const int mat = idx >> 12;
        const int n   = (idx >> 5) & 127;
        const int kk  = (idx >> 2) & 7;
        const int q   = idx & 3;
        const int k   = kk * 16 + q * 2;
        const float* W = mat ? Wv : Wk;
        float w0 = W[k * 128 + n],       w1 = W[(k + 1) * 128 + n];
        float w2 = W[(k + 8) * 128 + n], w3 = W[(k + 9) * 128 + n];
        uint4 v;
        v.x = packbf2(w0, w1);
        v.y = packbf2(w2, w3);
        v.z = packbf2(w0 - bfrt(w0), w1 - bfrt(w1));
        v.w = packbf2(w2 - bfrt(w2), w3 - bfrt(w3));
        g_Wfrag[idx] = v;
    } else if (idx < 12800) {
        const int j  = idx - 8192;
        const int n  = j / 36;
        const int rm = j % 36;
        const int kk = rm >> 2;
        const int q  = rm & 3;
        const int k  = kk * 16 + q * 2;
        float w0 = (k     < 130) ? Wq[(k)     * 128 + n] : 0.f;
        float w1 = (k + 1 < 130) ? Wq[(k + 1) * 128 + n] : 0.f;
        float w2 = (k + 8 < 130) ? Wq[(k + 8) * 128 + n] : 0.f;
        float w3 = (k + 9 < 130) ? Wq[(k + 9) * 128 + n] : 0.f;
        uint4 v;
        v.x = packbf2(w0, w1);
        v.y = packbf2(w2, w3);
        v.z = packbf2(w0 - bfrt(w0), w1 - bfrt(w1));
        v.w = packbf2(w2 - bfrt(w2), w3 - bfrt(w3));
        g_Wqfrag[j] = v;
    }
}

// ============================================================================
// Kernel 1: K/V = E @ W via mma.sync bf16 hi/lo split (round-14 version).
// ============================================================================
__global__ void __launch_bounds__(256, 2)
kv_mma_kernel(const float* __restrict__ E) {
    extern __shared__ __align__(16) float Es[];   // [128][132]
    const int tid  = threadIdx.x;
    const int wid  = tid >> 5;
    const int lane = tid & 31;
    const int R0   = blockIdx.x * 128;
    const int mat  = blockIdx.y;
    const int wr   = wid >> 1;
    const int wc   = wid & 1;

    for (int l = tid; l < 4096; l += 256) {
        int row = l >> 5, q = l & 31;
        cp16(&Es[row * 132 + q * 4], E + (R0 + row) * 128 + q * 4);
    }
    CP_COMMIT();

    float acc[2][8][4];
    #pragma unroll
    for (int mt = 0; mt < 2; ++mt)
        #pragma unroll
        for (int nt = 0; nt < 8; ++nt)
            #pragma unroll
            for (int i = 0; i < 4; ++i) acc[mt][nt][i] = 0.f;

    const int rfrag = lane >> 2;
    const int cfrag = (lane & 3) * 2;
    const uint4* Wf = g_Wfrag + mat * 4096;

    asm volatile("cp.async.wait_group 0;" ::: "memory");
    __syncthreads();

    #pragma unroll
    for (int kk = 0; kk < 8; ++kk) {
        unsigned ahi[2][4], alo[2][4];
        #pragma unroll
        for (int mt = 0; mt < 2; ++mt) {
            const float* r0p = &Es[(wr * 32 + mt * 16 + rfrag) * 132 + kk * 16 + cfrag];
            const float* r8p = r0p + 8 * 132;
            float2 x0 = *(const float2*)r0p;
            float2 x1 = *(const float2*)r8p;
            float2 x2 = *(const float2*)(r0p + 8);
            float2 x3 = *(const float2*)(r8p + 8);
            ahi[mt][0] = hipack(x0.x, x0.y);
            ahi[mt][1] = hipack(x1.x, x1.y);
            ahi[mt][2] = hipack(x2.x, x2.y);
            ahi[mt][3] = hipack(x3.x, x3.y);
            alo[mt][0] = packbf2(x0.x - hif(x0.x), x0.y - hif(x0.y));
            alo[mt][1] = packbf2(x1.x - hif(x1.x), x1.y - hif(x1.y));
            alo[mt][2] = packbf2(x2.x - hif(x2.x), x2.y - hif(x2.y));
            alo[mt][3] = packbf2(x3.x - hif(x3.x), x3.y - hif(x3.y));
        }
        #pragma unroll
        for (int nt = 0; nt < 8; ++nt) {
            const int n = wc * 64 + nt * 8 + rfrag;
            uint4 bf = Wf[(n * 8 + kk) * 4 + (lane & 3)];
            #pragma unroll
            for (int mt = 0; mt < 2; ++mt) {
                mma16816(acc[mt][nt][0], acc[mt][nt][1], acc[mt][nt][2], acc[mt][nt][3],
                         ahi[mt][0], ahi[mt][1], ahi[mt][2], ahi[mt][3], bf.x, bf.y);
                mma16816(acc[mt][nt][0], acc[mt][nt][1], acc[mt][nt][2], acc[mt][nt][3],
                         alo[mt][0], alo[mt][1], alo[mt][2], alo[mt][3], bf.x, bf.y);
                mma16816(acc[mt][nt][0], acc[mt][nt][1], acc[mt][nt][2], acc[mt][nt][3],
                         ahi[mt][0], ahi[mt][1], ahi[mt][2], ahi[mt][3], bf.z, bf.w);
            }
        }
    }

    float* dst = (mat ? g_V : g_K);
    #pragma unroll
    for (int mt = 0; mt < 2; ++mt) {
        const int row = R0 + wr * 32 + mt * 16 + rfrag;
        #pragma unroll
        for (int nt = 0; nt < 8; ++nt) {
            const int col = wc * 64 + nt * 8 + cfrag;
            *(float2*)(dst + (size_t)row * 128 + col)       = make_float2(acc[mt][nt][0], acc[mt][nt][1]);
            *(float2*)(dst + (size_t)(row + 8) * 128 + col) = make_float2(acc[mt][nt][2], acc[mt][nt][3]);
        }
    }
}

// ============================================================================
// Kernel 2: Q = concat(eln, load, time) @ Wq via mma.sync, 64-row tiles
// (validated round 12).
// ============================================================================
__global__ void __launch_bounds__(256)
q_mma_kernel(const float* __restrict__ eln,
             const float* __restrict__ loadv,
             const float* __restrict__ timev) {
    __shared__ __align__(16) float As[64][148];
    const int tid  = threadIdx.x;
    const int wid  = tid >> 5;
    const int lane = tid & 31;
    const int R0   = blockIdx.x * 64;
    const int wr   = wid >> 1;
    const int wc   = wid & 1;

    for (int l = tid; l < 2048; l += 256) {
        int row = l >> 5, q = l & 31;
        cp16(&As[row][q * 4], eln + (size_t)(R0 + row) * 128 + q * 4);
    }
    CP_COMMIT();
    for (int l = tid; l < 64 * 5; l += 256) {
        int row = l / 5, cq = (l % 5) * 4 + 128;
        float4 v = make_float4(0.f, 0.f, 0.f, 0.f);
        if (cq == 128) { v.x = loadv[R0 + row]; v.y = timev[R0 + row]; }
        *(float4*)&As[row][cq] = v;
    }

    float acc[8][4];
    #pragma unroll
    for (int nt = 0; nt < 8; ++nt)
        #pragma unroll
        for (int i = 0; i < 4; ++i) acc[nt][i] = 0.f;

    const int rfrag = lane >> 2;
    const int cfrag = (lane & 3) * 2;

    asm volatile("cp.async.wait_group 0;" ::: "memory");
    __syncthreads();

    #pragma unroll
    for (int kk = 0; kk < 9; ++kk) {
        unsigned ahi[4], alo[4];
        {
            const float* r0p = &As[wr * 16 + rfrag][kk * 16 + cfrag];
            const float* r8p = r0p + 8 * 148;
            float2 x0 = *(const float2*)r0p;
            float2 x1 = *(const float2*)r8p;
            float2 x2 = *(const float2*)(r0p + 8);
            float2 x3 = *(const float2*)(r8p + 8);
            ahi[0] = hipack(x0.x, x0.y);
            ahi[1] = hipack(x1.x, x1.y);
            ahi[2] = hipack(x2.x, x2.y);
            ahi[3] = hipack(x3.x, x3.y);
            alo[0] = packbf2(x0.x - hif(x0.x), x0.y - hif(x0.y));
            alo[1] = packbf2(x1.x - hif(x1.x), x1.y - hif(x1.y));
            alo[2] = packbf2(x2.x - hif(x2.x), x2.y - hif(x2.y));
            alo[3] = packbf2(x3.x - hif(x3.x), x3.y - hif(x3.y));
        }
        #pragma unroll
        for (int nt = 0; nt < 8; ++nt) {
            const int n = wc * 64 + nt * 8 + rfrag;
            uint4 bf = g_Wqfrag[(n * 9 + kk) * 4 + (lane & 3)];
            mma16816(acc[nt][0], acc[nt][1], acc[nt][2], acc[nt][3],
                     ahi[0], ahi[1], ahi[2], ahi[3], bf.x, bf.y);
            mma16816(acc[nt][0], acc[nt][1], acc[nt][2], acc[nt][3],
                     alo[0], alo[1], alo[2], alo[3], bf.x, bf.y);
            mma16816(acc[nt][0], acc[nt][1], acc[nt][2], acc[nt][3],
                     ahi[0], ahi[1], ahi[2], ahi[3], bf.z, bf.w);
        }
    }

    const int row = R0 + wr * 16 + rfrag;
    #pragma unroll
    for (int nt = 0; nt < 8; ++nt) {
        const int col = wc * 64 + nt * 8 + cfrag;
        *(float2*)(g_Q + (size_t)row * 128 + col)       = make_float2(acc[nt][0], acc[nt][1]);
        *(float2*)(g_Q + (size_t)(row + 8) * 128 + col) = make_float2(acc[nt][2], acc[nt][3]);
    }
}

// ============================================================================
// Kernel 3: attention via mma.sync, 4 splits of 256 n, shared fragment
// pre-packing (round-14 version).
// ============================================================================
__global__ void __launch_bounds__(224, 4)
attn_kernel() {
    const int bh    = blockIdx.x;
    const int split = blockIdx.y;
    const int b     = bh >> 3;
    const int h     = bh & 7;
    const int tid   = threadIdx.x;
    const int wid   = tid >> 5;
    const int lane  = tid & 31;
    const int rfrag = lane >> 2;
    const int c2    = (lane & 3) * 2;
    const int nbeg  = split * 256;

    __shared__ __align__(16) float Ks[2][64][16];
    __shared__ __align__(16) float Vs[2][64][16];
    __shared__ __align__(16) uint4 KB[2][64][4];
    __shared__ __align__(16) uint4 VB[2][256];

    const float* Kbase = g_K + b * 1000 * 128 + h * 16;
    const float* Vbase = g_V + b * 1000 * 128 + h * 16;

    for (int l = tid; l < 256; l += 224) {
        int j = l >> 2, qd = (l & 3) * 4;
        int n = nbeg + j; if (n > 999) n = 999;
        cp16(&Ks[0][j][qd], Kbase + n * 128 + qd);
        cp16(&Vs[0][j][qd], Vbase + n * 128 + qd);
    }
    CP_COMMIT();

    const int p0  = wid * 16 + rfrag;
    const int p1  = p0 + 8;
    const int pr0 = p0 < 100 ? p0 : 99;
    const int pr1 = p1 < 100 ? p1 : 99;
    unsigned qhi[4], qlo[4];
    {
        const float qs = 0.25f * LOG2E;
        const float* q0p = g_Q + (b * 100 + pr0) * 128 + h * 16;
        const float* q1p = g_Q + (b * 100 + pr1) * 128 + h * 16;
        float2 x0 = *(const float2*)(q0p + c2);
        float2 x1 = *(const float2*)(q1p + c2);
        float2 x2 = *(const float2*)(q0p + c2 + 8);
        float2 x3 = *(const float2*)(q1p + c2 + 8);
        float v0 = x0.x * qs, v1 = x0.y * qs, v2 = x1.x * qs, v3 = x1.y * qs;
        float v4 = x2.x * qs, v5 = x2.y * qs, v6 = x3.x * qs, v7 = x3.y * qs;
        qhi[0] = hipack(v0, v1); qhi[1] = hipack(v2, v3);
        qhi[2] = hipack(v4, v5); qhi[3] = hipack(v6, v7);
        qlo[0] = packbf2(v0 - hif(v0), v1 - hif(v1));
        qlo[1] = packbf2(v2 - hif(v2), v3 - hif(v3));
        qlo[2] = packbf2(v4 - hif(v4), v5 - hif(v5));
        qlo[3] = packbf2(v6 - hif(v6), v7 - hif(v7));
    }
    const unsigned* bw0 = g_bits + (b * 100 + pr0) * 32;
    const unsigned* bw1 = g_bits + (b * 100 + pr1) * 32;

    float acc[2][4];
    #pragma unroll
    for (int dt = 0; dt < 2; ++dt)
        #pragma unroll
        for (int i = 0; i < 4; ++i) acc[dt][i] = 0.f;
    float ls0 = 0.f, ls1 = 0.f;

    for (int t = 0; t < 4; ++t) {
        const int s    = t & 1;
        const int base = nbeg + t * 64;

        asm volatile("cp.async.wait_group 0;" ::: "memory");
        __syncthreads();

        for (int l = tid; l < 256; l += 224) {
            int row = l >> 2, q = l & 3;
            float2 a  = *(const float2*)&Ks[s][row][2 * q];
            float2 b2 = *(const float2*)&Ks[s][row][2 * q + 8];
            KB[s][row][q] = make_uint4(
                hipack(a.x, a.y), hipack(b2.x, b2.y),
                packbf2(a.x - hif(a.x), a.y - hif(a.y)),
                packbf2(b2.x - hif(b2.x), b2.y - hif(b2.y)));
        }
        for (int l = tid; l < 256; l += 224) {
            int kc = l >> 6, qq2 = (l >> 4) & 3, d = l & 15;
            int r0 = kc * 16 + 2 * qq2;
            float v0 = Vs[s][r0][d],     v1 = Vs[s][r0 + 1][d];
            float v2 = Vs[s][r0 + 8][d], v3 = Vs[s][r0 + 9][d];
            VB[s][l] = make_uint4(
                hipack(v0, v1), hipack(v2, v3),
                packbf2(v0 - hif(v0), v1 - hif(v1)),
                packbf2(v2 - hif(v2), v3 - hif(v3)));
        }

        if (t + 1 < 4) {
            const int ns = 1 - s, nb2 = base + 64;
            for (int l = tid; l < 256; l += 224) {
                int j = l >> 2, qd = (l & 3) * 4;
                int n = nb2 + j; if (n > 999) n = 999;
                cp16(&Ks[ns][j][qd], Kbase + n * 128 + qd);
                cp16(&Vs[ns][j][qd], Vbase + n * 128 + qd);
            }
            CP_COMMIT();
        }
        __syncthreads();

        const unsigned mw0a = bw0[base >> 5], mw0b = bw0[(base >> 5) + 1];
        const unsigned mw1a = bw1[base >> 5], mw1b = bw1[(base >> 5) + 1];

        #pragma unroll
        for (int kc = 0; kc < 4; ++kc) {
            unsigned phi[4], plo[4];
            #pragma unroll
            for (int jj = 0; jj < 2; ++jj) {
                const int j    = kc * 2 + jj;
                const int trow = j * 8 + rfrag;
                uint4 kf = KB[s][trow][lane & 3];
                float d0 = 0.f, d1 = 0.f, d2 = 0.f, d3 = 0.f;
                mma16816(d0, d1, d2, d3, qhi[0], qhi[1], qhi[2], qhi[3], kf.x, kf.y);
                mma16816(d0, d1, d2, d3, qlo[0], qlo[1], qlo[2], qlo[3], kf.x, kf.y);
                mma16816(d0, d1, d2, d3, qhi[0], qhi[1], qhi[2], qhi[3], kf.z, kf.w);

                const int nsel = j * 8 + c2;
                const int gn   = base + nsel;
                const unsigned w0 = (nsel < 32) ? mw0a : mw0b;
                const unsigned w1 = (nsel < 32) ? mw1a : mw1b;
                const int bit = nsel & 31;
                float e0 = ex2f(d0), e1 = ex2f(d1), e2 = ex2f(d2), e3 = ex2f(d3);
                if (((w0 >> bit) & 1u)       || gn >= 1000)     e0 = 0.f;
                if (((w0 >> (bit + 1)) & 1u) || gn + 1 >= 1000) e1 = 0.f;
                if (((w1 >> bit) & 1u)       || gn >= 1000)     e2 = 0.f;
                if (((w1 >> (bit + 1)) & 1u) || gn + 1 >= 1000) e3 = 0.f;
                ls0 += e0 + e1;
                ls1 += e2 + e3;
                phi[2 * jj]     = packbf2(e0, e1);
                phi[2 * jj + 1] = packbf2(e2, e3);
                plo[2 * jj]     = packbf2(e0 - bfrt(e0), e1 - bfrt(e1));
                plo[2 * jj + 1] = packbf2(e2 - bfrt(e2), e3 - bfrt(e3));
            }
            #pragma unroll
            for (int dt = 0; dt < 2; ++dt) {
                uint4 vf = VB[s][kc * 64 + (lane & 3) * 16 + dt * 8 + rfrag];
                mma16816(acc[dt][0], acc[dt][1], acc[dt][2], acc[dt][3],
                         phi[0], phi[1], phi[2], phi[3], vf.x, vf.y);
                mma16816(acc[dt][0], acc[dt][1], acc[dt][2], acc[dt][3],
                         plo[0], plo[1], plo[2], plo[3], vf.x, vf.y);
                mma16816(acc[dt][0], acc[dt][1], acc[dt][2], acc[dt][3],
                         phi[0], phi[1], phi[2], phi[3], vf.z, vf.w);
            }
        }
    }

    ls0 += __shfl_xor_sync(0xffffffffu, ls0, 1);
    ls0 += __shfl_xor_sync(0xffffffffu, ls0, 2);
    ls1 += __shfl_xor_sync(0xffffffffu, ls1, 1);
    ls1 += __shfl_xor_sync(0xffffffffu, ls1, 2);

    if (p0 < 100) {
        float* pp = g_part + ((split * 512 + bh) * 100 + p0) * 17;
        pp[c2]     = acc[0][0]; pp[c2 + 1]     = acc[0][1];
        pp[8 + c2] = acc[1][0]; pp[8 + c2 + 1] = acc[1][1];
        if ((lane & 3) == 0) pp[16] = ls0;
    }
    if (p1 < 100) {
        float* pp = g_part + ((split * 512 + bh) * 100 + p1) * 17;
        pp[c2]     = acc[0][2]; pp[c2 + 1]     = acc[0][3];
        pp[8 + c2] = acc[1][2]; pp[8 + c2 + 1] = acc[1][3];
        if ((lane & 3) == 0) pp[16] = ls1;
    }
}

// ============================================================================
// Kernel 4: fused combine (4 splits) + MH = (normalized O) @ Wc + bc
// ============================================================================
__global__ void __launch_bounds__(256)
mh_kernel(const float* __restrict__ Wc, const float* __restrict__ bc) {
    __shared__ float As[128][20];
    __shared__ float sinv[16][8];
    const int tid = threadIdx.x;
    const int R0  = blockIdx.x * 16;
    const int tx  = tid & 63;
    const int ty  = tid >> 6;

    if (tid < 128) {
        int row = tid >> 3, h = tid & 7;
        int gr = R0 + row;
        int b = gr / 100, p = gr % 100;
        int bh = b * 8 + h;
        float ls = 0.f;
        #pragma unroll
        for (int sp = 0; sp < 4; ++sp)
            ls += g_part[((sp * 512 + bh) * 100 + p) * 17 + 16];
        sinv[row][h] = 1.f / ls;
    }
    __syncthreads();

    for (int l = tid; l < 2048; l += 256) {
        int row = l >> 7, col = l & 127;
        int gr = R0 + row;
        int b = gr / 100, p = gr % 100;
        int h = col >> 4, d = col & 15;
        int bh = b * 8 + h;
        float s = 0.f;
        #pragma unroll
        for (int sp = 0; sp < 4; ++sp)
            s += g_part[((sp * 512 + bh) * 100 + p) * 17 + d];
        As[col][row] = s * sinv[row][h];
    }
    __syncthreads();

    u64t acc[4];
    {
        float2 bb = *(const float2*)(bc + tx * 2);
        u64t bb2; asm("mov.b64 %0, {%1, %2};" : "=l"(bb2) : "f"(bb.x), "f"(bb.y));
        acc[0] = bb2; acc[1] = bb2; acc[2] = bb2; acc[3] = bb2;
    }

    #pragma unroll 8
    for (int k = 0; k < 128; ++k) {
        u64t w = *(const u64t*)(Wc + k * 128 + tx * 2);
        float4 a = *(const float4*)&As[k][ty * 4];
        acc[0] = fma2(splat2(a.x), w, acc[0]);
        acc[1] = fma2(splat2(a.y), w, acc[1]);
        acc[2] = fma2(splat2(a.z), w, acc[2]);
        acc[3] = fma2(splat2(a.w), w, acc[3]);
    }

    #pragma unroll
    for (int r = 0; r < 4; ++r)
        *(u64t*)(g_MH + (R0 + ty * 4 + r) * 128 + tx * 2) = acc[r];
}

// ============================================================================
// Kernel 5: score = MH @ E^T via mma.sync with cooperative E fragment
// pre-packing (validated round 14).
// ============================================================================
__global__ void __launch_bounds__(224, 2)
score_kernel(const float* __restrict__ Enodes,
             const float* __restrict__ cur_dist,
             const float* __restrict__ noise,
             float* __restrict__ out) {
    extern __shared__ __align__(16) uint4 EB[];   // [128][33]
    const int tid   = threadIdx.x;
    const int wid   = tid >> 5;
    const int lane  = tid & 31;
    const int rfrag = lane >> 2;
    const int c2    = (lane & 3) * 2;
    const int n0    = blockIdx.x * 128;
    const int b     = blockIdx.y;

    for (int l = tid; l < 4096; l += 224) {
        const int n  = l >> 5;
        const int j  = l & 31;
        const int k  = (j >> 2) * 16 + (j & 3) * 2;
        int gn = n0 + n; if (gn > 999) gn = 999;
        const float* ep = Enodes + (size_t)(b * 1000 + gn) * 128 + k;
        float2 a  = *(const float2*)ep;
        float2 c  = *(const float2*)(ep + 8);
        EB[n * 33 + j] = make_uint4(
            hipack(a.x, a.y), hipack(c.x, c.y),
            packbf2(a.x - hif(a.x), a.y - hif(a.y)),
            packbf2(c.x - hif(c.x), c.y - hif(c.y)));
    }
    __syncthreads();

    const int p0  = wid * 16 + rfrag;
    const int p1  = p0 + 8;
    const int pr0 = p0 < 100 ? p0 : 99;
    const int pr1 = p1 < 100 ? p1 : 99;
    const float* m0base = g_MH + (size_t)(b * 100 + pr0) * 128;
    const float* m1base = g_MH + (size_t)(b * 100 + pr1) * 128;

    float acc[16][4];
    #pragma unroll
    for (int nt = 0; nt < 16; ++nt)
        #pragma unroll
        for (int i = 0; i < 4; ++i) acc[nt][i] = 0.f;

    #pragma unroll
    for (int kk = 0; kk < 8; ++kk) {
        unsigned ahi[4], alo[4];
        {
            float2 x0 = *(const float2*)(m0base + kk * 16 + c2);
            float2 x1 = *(const float2*)(m1base + kk * 16 + c2);
            float2 x2 = *(const float2*)(m0base + kk * 16 + c2 + 8);
            float2 x3 = *(const float2*)(m1base + kk * 16 + c2 + 8);
            ahi[0] = hipack(x0.x, x0.y); ahi[1] = hipack(x1.x, x1.y);
            ahi[2] = hipack(x2.x, x2.y); ahi[3] = hipack(x3.x, x3.y);
            alo[0] = packbf2(x0.x - hif(x0.x), x0.y - hif(x0.y));
            alo[1] = packbf2(x1.x - hif(x1.x), x1.y - hif(x1.y));
            alo[2] = packbf2(x2.x - hif(x2.x), x2.y - hif(x2.y));
            alo[3] = packbf2(x3.x - hif(x3.x), x3.y - hif(x3.y));
        }
        #pragma unroll
        for (int nt = 0; nt < 16; ++nt) {
            uint4 bf = EB[(nt * 8 + rfrag) * 33 + kk * 4 + (lane & 3)];
            mma16816(acc[nt][0], acc[nt][1], acc[nt][2], acc[nt][3],
                     ahi[0], ahi[1], ahi[2], ahi[3], bf.x, bf.y);
            mma16816(acc[nt][0], acc[nt][1], acc[nt][2], acc[nt][3],
                     alo[0], alo[1], alo[2], alo[3], bf.x, bf.y);
            mma16816(acc[nt][0], acc[nt][1], acc[nt][2], acc[nt][3],
                     ahi[0], ahi[1], ahi[2], ahi[3], bf.z, bf.w);
        }
    }

    #pragma unroll
    for (int nt = 0; nt < 16; ++nt) {
        const int cn = n0 + nt * 8 + c2;
        if (cn < 1000) {
            #pragma unroll
            for (int dt = 0; dt < 2; ++dt) {
                const int p = dt ? p1 : p0;
                if (p < 100) {
                    const int idx = (b * 100 + p) * 1000 + cn;
                    float2 cd = *(const float2*)(cur_dist + idx);
                    float2 nz = *(const float2*)(noise + idx);
                    float s0 = acc[nt][dt * 2 + 0];
                    float s1 = acc[nt][dt * 2 + 1];
                    float h0 = -__logf(fmaf(2.f, cd.x, 1e-6f));
                    float h1 = -__logf(fmaf(2.f, cd.y, 1e-6f));
                    float r0 = tanh_scaled(s0 * INV_SQRT_EMB + A_COEF * h0 + B_COEF * nz.x, 10.f);
                    float r1 = tanh_scaled(s1 * INV_SQRT_EMB + A_COEF * h1 + B_COEF * nz.y, 10.f);
                    *(float2*)(out + idx) = make_float2(r0, r1);
                }
            }
        }
    }
}

// ============================================================================
// Kernel 6: masked in-place row softmax, M=10, float4 path; mask word
// straight from L2 (no smem staging / extra barrier).
// ============================================================================
__global__ void __launch_bounds__(256)
softmax_kernel(float* __restrict__ out) {
    const int row = blockIdx.x;
    const int tid = threadIdx.x;
    float* sp = out + row * 1000;

    __shared__ float ssum[8];

    float e0 = 0.f, e1 = 0.f, e2 = 0.f, e3 = 0.f, lsum = 0.f;
    if (tid < 250) {
        float4 v = *(const float4*)(sp + tid * 4);
        const unsigned w  = __ldg(&g_bits[row * 32 + (tid >> 3)]);
        const int      sh = (tid * 4) & 31;
        e0 = ((w >> sh)       & 1u) ? 0.f : __expf(v.x - 10.f);
        e1 = ((w >> (sh + 1)) & 1u) ? 0.f : __expf(v.y - 10.f);
        e2 = ((w >> (sh + 2)) & 1u) ? 0.f : __expf(v.z - 10.f);
        e3 = ((w >> (sh + 3)) & 1u) ? 0.f : __expf(v.w - 10.f);
        lsum = (e0 + e1) + (e2 + e3);
    }
    #pragma unroll
    for (int o = 16; o; o >>= 1) lsum += __shfl_xor_sync(0xffffffffu, lsum, o);
    if ((tid & 31) == 0) ssum[tid >> 5] = lsum;
    __syncthreads();
    float S = 0.f;
    #pragma unroll
    for (int w = 0; w < 8; ++w) S += ssum[w];

    const float inv = 1.f / S;
    if (tid < 250)
        *(float4*)(sp + tid * 4) = make_float4(e0 * inv, e1 * inv, e2 * inv, e3 * inv);
}

// ============================================================================
extern "C" void kernel_launch(void* const* d_in, const int* in_sizes, int n_in,
                              void* d_out, int out_size) {
    const float* eln      = (const float*)d_in[0];
    const float* loadv    = (const float*)d_in[1];
    const float* timev    = (const float*)d_in[2];
    const float* cur_dist = (const float*)d_in[3];
    const float* ninf     = (const float*)d_in[4];
    const float* noise    = (const float*)d_in[5];
    const float* Enodes   = (const float*)d_in[6];
    const float* Wq       = (const float*)d_in[7];
    const float* Wk       = (const float*)d_in[8];
    const float* Wv       = (const float*)d_in[9];
    const float* Wc       = (const float*)d_in[10];
    const float* bc       = (const float*)d_in[11];
    float* out = (float*)d_out;

    const int KV_SMEM = 128 * 132 * 4;   // 67584 B
    const int SC_SMEM = 128 * 33 * 16;   // 67584 B
    cudaFuncSetAttribute(kv_mma_kernel, cudaFuncAttributeMaxDynamicSharedMemorySize, KV_SMEM);
    cudaFuncSetAttribute(score_kernel,  cudaFuncAttributeMaxDynamicSharedMemorySize, SC_SMEM);

    bits_kernel<<<25600, 256>>>(ninf);
    wprep_kernel<<<50, 256>>>(Wk, Wv, Wq);
    kv_mma_kernel<<<dim3(500, 2), 256, KV_SMEM>>>(Enodes);
    q_mma_kernel<<<100, 256>>>(eln, loadv, timev);
    attn_kernel<<<dim3(512, 4), 224>>>();
    mh_kernel<<<400, 256>>>(Wc, bc);
    score_kernel<<<dim3(8, 64), 224, SC_SMEM>>>(Enodes, cur_dist, noise, out);
    softmax_kernel<<<6400, 256>>>(out);
}

// round 17
// speedup vs baseline: 1.1513x; 1.0423x over previous
#include <cuda_runtime.h>
#include <cuda_bf16.h>
#include <math.h>
#include <stdint.h>

#define Bc   64
#define Pc   100
#define Nc   1000
#define EMBc 128

// ---- scratch (__device__ globals; no allocation allowed) ----
__device__ __align__(16) float g_K[Bc * Nc * EMBc];
__device__ __align__(16) float g_V[Bc * Nc * EMBc];
__device__ __align__(16) float g_Q[Bc * Pc * EMBc];
__device__ __align__(16) float g_MH[Bc * Pc * EMBc];
__device__ __align__(16) unsigned g_bits[Bc * Pc * 32];
__device__ __align__(16) float g_part[4 * 512 * Pc * 17];
// W in mma.sync B-fragment order: [mat][n(128)][kk(8)][q(4)] x uint4{b0h,b1h,b0l,b1l}
__device__ __align__(16) uint4 g_Wfrag[2 * 128 * 8 * 4];
// Wq frags: [n(128)][kk(9)][q(4)] (k padded 130 -> 144)
__device__ __align__(16) uint4 g_Wqfrag[128 * 9 * 4];

constexpr double X218   = 3.814697265625e-06;
constexpr float  A_COEF = (float)(1.0 / (1.0 + X218));
constexpr float  B_COEF = (float)(1.0 - 1.0 / (1.0 + X218));
constexpr float  INV_SQRT_EMB = 0.08838834764831845f;
constexpr float  LOG2E = 1.44269504088896340736f;

// ---- packed fp32x2 helpers ----
typedef unsigned long long u64t;
__device__ __forceinline__ u64t fma2(u64t a, u64t b, u64t c) {
    u64t d; asm("fma.rn.f32x2 %0, %1, %2, %3;" : "=l"(d) : "l"(a), "l"(b), "l"(c)); return d;
}
__device__ __forceinline__ u64t splat2(float x) {
    u64t d; asm("mov.b64 %0, {%1, %1};" : "=l"(d) : "f"(x)); return d;
}
__device__ __forceinline__ float2 unpack2(u64t v) {
    float2 r; asm("mov.b64 {%0, %1}, %2;" : "=f"(r.x), "=f"(r.y) : "l"(v)); return r;
}
__device__ __forceinline__ float ex2f(float x) {
    float r; asm("ex2.approx.f32 %0, %1;" : "=f"(r) : "f"(x)); return r;
}
__device__ __forceinline__ float rcpf(float x) {
    float r; asm("rcp.approx.f32 %0, %1;" : "=f"(r) : "f"(x)); return r;
}
__device__ __forceinline__ float tanh_scaled(float x, float scale) {
    float t = ex2f(x * (2.f * LOG2E));
    float num = t - 1.f, den = t + 1.f;
    float r = rcpf(den);
    r = r * (2.f - den * r);
    return num * r * scale;
}

// ---- cp.async ----
__device__ __forceinline__ void cp16(void* dst, const void* src) {
    unsigned d = (unsigned)__cvta_generic_to_shared(dst);
    asm volatile("cp.async.cg.shared.global [%0], [%1], 16;" :: "r"(d), "l"(src));
}
#define CP_COMMIT() asm volatile("cp.async.commit_group;" ::: "memory")

// ---- bf16 split helpers ----
__device__ __forceinline__ unsigned packbf2(float a, float b) {
    __nv_bfloat162 v = __floats2bfloat162_rn(a, b);
    return *reinterpret_cast<unsigned*>(&v);
}
__device__ __forceinline__ float bfrt(float x) {
    return __bfloat162float(__float2bfloat16(x));
}
__device__ __forceinline__ unsigned hipack(float a, float b) {
    unsigned r;
    asm("prmt.b32 %0, %1, %2, 0x7632;" : "=r"(r)
        : "r"(__float_as_uint(a)), "r"(__float_as_uint(b)));
    return r;
}
__device__ __forceinline__ float hif(float x) {
    return __uint_as_float(__float_as_uint(x) & 0xFFFF0000u);
}

// ---- mma.sync m16n8k16 bf16, fp32 accum ----
__device__ __forceinline__ void mma16816(float& d0, float& d1, float& d2, float& d3,
                                         unsigned a0, unsigned a1, unsigned a2, unsigned a3,
                                         unsigned b0, unsigned b1) {
    asm volatile(
        "mma.sync.aligned.m16n8k16.row.col.f32.bf16.bf16.f32 "
        "{%0,%1,%2,%3}, {%4,%5,%6,%7}, {%8,%9}, {%0,%1,%2,%3};"
        : "+f"(d0), "+f"(d1), "+f"(d2), "+f"(d3)
        : "r"(a0), "r"(a1), "r"(a2), "r"(a3), "r"(b0), "r"(b1));
}

// ============================================================================
// Kernel 0: pack ninf mask into bits (1 = masked).
// ============================================================================
__global__ void bits_kernel(const float* __restrict__ ninf) {
    const int w = blockIdx.x * 8 + (threadIdx.x >> 5);
    if (w >= Bc * Pc * 32) return;
    const int lane = threadIdx.x & 31;
    const int row = w >> 5, word = w & 31;
    const int n = word * 32 + lane;
    float v = -1.f;
    if (n < 1000) v = ninf[row * 1000 + n];
    unsigned m = __ballot_sync(0xffffffffu, v < -0.5f);
    if (lane == 0) g_bits[w] = m;
}

// ============================================================================
// Kernel 0b: pack Wk/Wv (8192) + Wq (4608) into B-fragment order, hi/lo split.
// ============================================================================
__global__ void wprep_kernel(const float* __restrict__ Wk, const float* __restrict__ Wv,
                             const float* __restrict__ Wq) {
    int idx = blockIdx.x * 256 + threadIdx.x;   // 12800 total
    if (idx < 8192) {
        const int mat = idx >> 12;
        const int n   = (idx >> 5) & 127;
        const int kk  = (idx >> 2) & 7;
        const int q   = idx & 3;
        const int k   = kk * 16 + q * 2;
        const float* W = mat ? Wv : Wk;
        float w0 = W[k * 128 + n],       w1 = W[(k + 1) * 128 + n];
        float w2 = W[(k + 8) * 128 + n], w3 = W[(k + 9) * 128 + n];
        uint4 v;
        v.x = packbf2(w0, w1);
        v.y = packbf2(w2, w3);
        v.z = packbf2(w0 - bfrt(w0), w1 - bfrt(w1));
        v.w = packbf2(w2 - bfrt(w2), w3 - bfrt(w3));
        g_Wfrag[idx] = v;
    } else if (idx < 12800) {
        const int j  = idx - 8192;
        const int n  = j / 36;
        const int rm = j % 36;
        const int kk = rm >> 2;
        const int q  = rm & 3;
        const int k  = kk * 16 + q * 2;
        float w0 = (k     < 130) ? Wq[(k)     * 128 + n] : 0.f;
        float w1 = (k + 1 < 130) ? Wq[(k + 1) * 128 + n] : 0.f;
        float w2 = (k + 8 < 130) ? Wq[(k + 8) * 128 + n] : 0.f;
        float w3 = (k + 9 < 130) ? Wq[(k + 9) * 128 + n] : 0.f;
        uint4 v;
        v.x = packbf2(w0, w1);
        v.y = packbf2(w2, w3);
        v.z = packbf2(w0 - bfrt(w0), w1 - bfrt(w1));
        v.w = packbf2(w2 - bfrt(w2), w3 - bfrt(w3));
        g_Wqfrag[j] = v;
    }
}

// ============================================================================
// Kernel 1: fused K/V + Q projections. Blocks 0..999: K/V = E @ {Wk,Wv}
// (round-14 kv path, tile=blk>>1, mat=blk&1). Blocks 1000..1099: Q =
// concat(eln,load,time) @ Wq (round-12 q path). Q blocks back-fill kv's tail.
// ============================================================================
__global__ void __launch_bounds__(256, 2)
kvq_mma_kernel(const float* __restrict__ E,
               const float* __restrict__ eln,
               const float* __restrict__ loadv,
               const float* __restrict__ timev) {
    extern __shared__ __align__(16) float Es[];
    const int tid  = threadIdx.x;
    const int wid  = tid >> 5;
    const int lane = tid & 31;
    const int rfrag = lane >> 2;
    const int cfrag = (lane & 3) * 2;
    const int blk  = blockIdx.x;

    if (blk < 1000) {
        // ---------------- K/V path (layout: Es[128][132]) ----------------
        const int R0  = (blk >> 1) * 128;
        const int mat = blk & 1;
        const int wr  = wid >> 1;
        const int wc  = wid & 1;

        for (int l = tid; l < 4096; l += 256) {
            int row = l >> 5, q = l & 31;
            cp16(&Es[row * 132 + q * 4], E + (R0 + row) * 128 + q * 4);
        }
        CP_COMMIT();

        float acc[2][8][4];
        #pragma unroll
        for (int mt = 0; mt < 2; ++mt)
            #pragma unroll
            for (int nt = 0; nt < 8; ++nt)
                #pragma unroll
                for (int i = 0; i < 4; ++i) acc[mt][nt][i] = 0.f;

        const uint4* Wf = g_Wfrag + mat * 4096;

        asm volatile("cp.async.wait_group 0;" ::: "memory");
        __syncthreads();

        #pragma unroll
        for (int kk = 0; kk < 8; ++kk) {
            unsigned ahi[2][4], alo[2][4];
            #pragma unroll
            for (int mt = 0; mt < 2; ++mt) {
                const float* r0p = &Es[(wr * 32 + mt * 16 + rfrag) * 132 + kk * 16 + cfrag];
                const float* r8p = r0p + 8 * 132;
                float2 x0 = *(const float2*)r0p;
                float2 x1 = *(const float2*)r8p;
                float2 x2 = *(const float2*)(r0p + 8);
                float2 x3 = *(const float2*)(r8p + 8);
                ahi[mt][0] = hipack(x0.x, x0.y);
                ahi[mt][1] = hipack(x1.x, x1.y);
                ahi[mt][2] = hipack(x2.x, x2.y);
                ahi[mt][3] = hipack(x3.x, x3.y);
                alo[mt][0] = packbf2(x0.x - hif(x0.x), x0.y - hif(x0.y));
                alo[mt][1] = packbf2(x1.x - hif(x1.x), x1.y - hif(x1.y));
                alo[mt][2] = packbf2(x2.x - hif(x2.x), x2.y - hif(x2.y));
                alo[mt][3] = packbf2(x3.x - hif(x3.x), x3.y - hif(x3.y));
            }
            #pragma unroll
            for (int nt = 0; nt < 8; ++nt) {
                const int n = wc * 64 + nt * 8 + rfrag;
                uint4 bf = Wf[(n * 8 + kk) * 4 + (lane & 3)];
                #pragma unroll
                for (int mt = 0; mt < 2; ++mt) {
                    mma16816(acc[mt][nt][0], acc[mt][nt][1], acc[mt][nt][2], acc[mt][nt][3],
                             ahi[mt][0], ahi[mt][1], ahi[mt][2], ahi[mt][3], bf.x, bf.y);
                    mma16816(acc[mt][nt][0], acc[mt][nt][1], acc[mt][nt][2], acc[mt][nt][3],
                             alo[mt][0], alo[mt][1], alo[mt][2], alo[mt][3], bf.x, bf.y);
                    mma16816(acc[mt][nt][0], acc[mt][nt][1], acc[mt][nt][2], acc[mt][nt][3],
                             ahi[mt][0], ahi[mt][1], ahi[mt][2], ahi[mt][3], bf.z, bf.w);
                }
            }
        }

        float* dst = (mat ? g_V : g_K);
        #pragma unroll
        for (int mt = 0; mt < 2; ++mt) {
            const int row = R0 + wr * 32 + mt * 16 + rfrag;
            #pragma unroll
            for (int nt = 0; nt < 8; ++nt) {
                const int col = wc * 64 + nt * 8 + cfrag;
                *(float2*)(dst + (size_t)row * 128 + col)       = make_float2(acc[mt][nt][0], acc[mt][nt][1]);
                *(float2*)(dst + (size_t)(row + 8) * 128 + col) = make_float2(acc[mt][nt][2], acc[mt][nt][3]);
            }
        }
    } else {
        // ---------------- Q path (layout: Es[64][148]) ----------------
        const int R0 = (blk - 1000) * 64;
        const int wr = wid >> 1;
        const int wc = wid & 1;

        for (int l = tid; l < 2048; l += 256) {
            int row = l >> 5, q = l & 31;
            cp16(&Es[row * 148 + q * 4], eln + (size_t)(R0 + row) * 128 + q * 4);
        }
        CP_COMMIT();
        for (int l = tid; l < 64 * 5; l += 256) {
            int row = l / 5, cq = (l % 5) * 4 + 128;
            float4 v = make_float4(0.f, 0.f, 0.f, 0.f);
            if (cq == 128) { v.x = loadv[R0 + row]; v.y = timev[R0 + row]; }
            *(float4*)&Es[row * 148 + cq] = v;
        }

        float acc[8][4];
        #pragma unroll
        for (int nt = 0; nt < 8; ++nt)
            #pragma unroll
            for (int i = 0; i < 4; ++i) acc[nt][i] = 0.f;

        asm volatile("cp.async.wait_group 0;" ::: "memory");
        __syncthreads();

        #pragma unroll
        for (int kk = 0; kk < 9; ++kk) {
            unsigned ahi[4], alo[4];
            {
                const float* r0p = &Es[(wr * 16 + rfrag) * 148 + kk * 16 + cfrag];
                const float* r8p = r0p + 8 * 148;
                float2 x0 = *(const float2*)r0p;
                float2 x1 = *(const float2*)r8p;
                float2 x2 = *(const float2*)(r0p + 8);
                float2 x3 = *(const float2*)(r8p + 8);
                ahi[0] = hipack(x0.x, x0.y);
                ahi[1] = hipack(x1.x, x1.y);
                ahi[2] = hipack(x2.x, x2.y);
                ahi[3] = hipack(x3.x, x3.y);
                alo[0] = packbf2(x0.x - hif(x0.x), x0.y - hif(x0.y));
                alo[1] = packbf2(x1.x - hif(x1.x), x1.y - hif(x1.y));
                alo[2] = packbf2(x2.x - hif(x2.x), x2.y - hif(x2.y));
                alo[3] = packbf2(x3.x - hif(x3.x), x3.y - hif(x3.y));
            }
            #pragma unroll
            for (int nt = 0; nt < 8; ++nt) {
                const int n = wc * 64 + nt * 8 + rfrag;
                uint4 bf = g_Wqfrag[(n * 9 + kk) * 4 + (lane & 3)];
                mma16816(acc[nt][0], acc[nt][1], acc[nt][2], acc[nt][3],
                         ahi[0], ahi[1], ahi[2], ahi[3], bf.x, bf.y);
                mma16816(acc[nt][0], acc[nt][1], acc[nt][2], acc[nt][3],
                         alo[0], alo[1], alo[2], alo[3], bf.x, bf.y);
                mma16816(acc[nt][0], acc[nt][1], acc[nt][2], acc[nt][3],
                         ahi[0], ahi[1], ahi[2], ahi[3], bf.z, bf.w);
            }
        }

        const int row = R0 + wr * 16 + rfrag;
        #pragma unroll
        for (int nt = 0; nt < 8; ++nt) {
            const int col = wc * 64 + nt * 8 + cfrag;
            *(float2*)(g_Q + (size_t)row * 128 + col)       = make_float2(acc[nt][0], acc[nt][1]);
            *(float2*)(g_Q + (size_t)(row + 8) * 128 + col) = make_float2(acc[nt][2], acc[nt][3]);
        }
    }
}

// ============================================================================
// Kernel 3: attention via mma.sync, 4 splits of 256 n, shared fragment
// pre-packing (validated rounds 13-16).
// ============================================================================
__global__ void __launch_bounds__(224, 4)
attn_kernel() {
    const int bh    = blockIdx.x;
    const int split = blockIdx.y;
    const int b     = bh >> 3;
    const int h     = bh & 7;
    const int tid   = threadIdx.x;
    const int wid   = tid >> 5;
    const int lane  = tid & 31;
    const int rfrag = lane >> 2;
    const int c2    = (lane & 3) * 2;
    const int nbeg  = split * 256;

    __shared__ __align__(16) float Ks[2][64][16];
    __shared__ __align__(16) float Vs[2][64][16];
    __shared__ __align__(16) uint4 KB[2][64][4];
    __shared__ __align__(16) uint4 VB[2][256];

    const float* Kbase = g_K + b * 1000 * 128 + h * 16;
    const float* Vbase = g_V + b * 1000 * 128 + h * 16;

    for (int l = tid; l < 256; l += 224) {
        int j = l >> 2, qd = (l & 3) * 4;
        int n = nbeg + j; if (n > 999) n = 999;
        cp16(&Ks[0][j][qd], Kbase + n * 128 + qd);
        cp16(&Vs[0][j][qd], Vbase + n * 128 + qd);
    }
    CP_COMMIT();

    const int p0  = wid * 16 + rfrag;
    const int p1  = p0 + 8;
    const int pr0 = p0 < 100 ? p0 : 99;
    const int pr1 = p1 < 100 ? p1 : 99;
    unsigned qhi[4], qlo[4];
    {
        const float qs = 0.25f * LOG2E;
        const float* q0p = g_Q + (b * 100 + pr0) * 128 + h * 16;
        const float* q1p = g_Q + (b * 100 + pr1) * 128 + h * 16;
        float2 x0 = *(const float2*)(q0p + c2);
        float2 x1 = *(const float2*)(q1p + c2);
        float2 x2 = *(const float2*)(q0p + c2 + 8);
        float2 x3 = *(const float2*)(q1p + c2 + 8);
        float v0 = x0.x * qs, v1 = x0.y * qs, v2 = x1.x * qs, v3 = x1.y * qs;
        float v4 = x2.x * qs, v5 = x2.y * qs, v6 = x3.x * qs, v7 = x3.y * qs;
        qhi[0] = hipack(v0, v1); qhi[1] = hipack(v2, v3);
        qhi[2] = hipack(v4, v5); qhi[3] = hipack(v6, v7);
        qlo[0] = packbf2(v0 - hif(v0), v1 - hif(v1));
        qlo[1] = packbf2(v2 - hif(v2), v3 - hif(v3));
        qlo[2] = packbf2(v4 - hif(v4), v5 - hif(v5));
        qlo[3] = packbf2(v6 - hif(v6), v7 - hif(v7));
    }
    const unsigned* bw0 = g_bits + (b * 100 + pr0) * 32;
    const unsigned* bw1 = g_bits + (b * 100 + pr1) * 32;

    float acc[2][4];
    #pragma unroll
    for (int dt = 0; dt < 2; ++dt)
        #pragma unroll
        for (int i = 0; i < 4; ++i) acc[dt][i] = 0.f;
    float ls0 = 0.f, ls1 = 0.f;

    for (int t = 0; t < 4; ++t) {
        const int s    = t & 1;
        const int base = nbeg + t * 64;

        asm volatile("cp.async.wait_group 0;" ::: "memory");
        __syncthreads();

        for (int l = tid; l < 256; l += 224) {
            int row = l >> 2, q = l & 3;
            float2 a  = *(const float2*)&Ks[s][row][2 * q];
            float2 b2 = *(const float2*)&Ks[s][row][2 * q + 8];
            KB[s][row][q] = make_uint4(
                hipack(a.x, a.y), hipack(b2.x, b2.y),
                packbf2(a.x - hif(a.x), a.y - hif(a.y)),
                packbf2(b2.x - hif(b2.x), b2.y - hif(b2.y)));
        }
        for (int l = tid; l < 256; l += 224) {
            int kc = l >> 6, qq2 = (l >> 4) & 3, d = l & 15;
            int r0 = kc * 16 + 2 * qq2;
            float v0 = Vs[s][r0][d],     v1 = Vs[s][r0 + 1][d];
            float v2 = Vs[s][r0 + 8][d], v3 = Vs[s][r0 + 9][d];
            VB[s][l] = make_uint4(
                hipack(v0, v1), hipack(v2, v3),
                packbf2(v0 - hif(v0), v1 - hif(v1)),
                packbf2(v2 - hif(v2), v3 - hif(v3)));
        }

        if (t + 1 < 4) {
            const int ns = 1 - s, nb2 = base + 64;
            for (int l = tid; l < 256; l += 224) {
                int j = l >> 2, qd = (l & 3) * 4;
                int n = nb2 + j; if (n > 999) n = 999;
                cp16(&Ks[ns][j][qd], Kbase + n * 128 + qd);
                cp16(&Vs[ns][j][qd], Vbase + n * 128 + qd);
            }
            CP_COMMIT();
        }
        __syncthreads();

        const unsigned mw0a = bw0[base >> 5], mw0b = bw0[(base >> 5) + 1];
        const unsigned mw1a = bw1[base >> 5], mw1b = bw1[(base >> 5) + 1];

        #pragma unroll
        for (int kc = 0; kc < 4; ++kc) {
            unsigned phi[4], plo[4];
            #pragma unroll
            for (int jj = 0; jj < 2; ++jj) {
                const int j    = kc * 2 + jj;
                const int trow = j * 8 + rfrag;
                uint4 kf = KB[s][trow][lane & 3];
                float d0 = 0.f, d1 = 0.f, d2 = 0.f, d3 = 0.f;
                mma16816(d0, d1, d2, d3, qhi[0], qhi[1], qhi[2], qhi[3], kf.x, kf.y);
                mma16816(d0, d1, d2, d3, qlo[0], qlo[1], qlo[2], qlo[3], kf.x, kf.y);
                mma16816(d0, d1, d2, d3, qhi[0], qhi[1], qhi[2], qhi[3], kf.z, kf.w);

                const int nsel = j * 8 + c2;
                const int gn   = base + nsel;
                const unsigned w0 = (nsel < 32) ? mw0a : mw0b;
                const unsigned w1 = (nsel < 32) ? mw1a : mw1b;
                const int bit = nsel & 31;
                float e0 = ex2f(d0), e1 = ex2f(d1), e2 = ex2f(d2), e3 = ex2f(d3);
                if (((w0 >> bit) & 1u)       || gn >= 1000)     e0 = 0.f;
                if (((w0 >> (bit + 1)) & 1u) || gn + 1 >= 1000) e1 = 0.f;
                if (((w1 >> bit) & 1u)       || gn >= 1000)     e2 = 0.f;
                if (((w1 >> (bit + 1)) & 1u) || gn + 1 >= 1000) e3 = 0.f;
                ls0 += e0 + e1;
                ls1 += e2 + e3;
                phi[2 * jj]     = packbf2(e0, e1);
                phi[2 * jj + 1] = packbf2(e2, e3);
                plo[2 * jj]     = packbf2(e0 - bfrt(e0), e1 - bfrt(e1));
                plo[2 * jj + 1] = packbf2(e2 - bfrt(e2), e3 - bfrt(e3));
            }
            #pragma unroll
            for (int dt = 0; dt < 2; ++dt) {
                uint4 vf = VB[s][kc * 64 + (lane & 3) * 16 + dt * 8 + rfrag];
                mma16816(acc[dt][0], acc[dt][1], acc[dt][2], acc[dt][3],
                         phi[0], phi[1], phi[2], phi[3], vf.x, vf.y);
                mma16816(acc[dt][0], acc[dt][1], acc[dt][2], acc[dt][3],
                         plo[0], plo[1], plo[2], plo[3], vf.x, vf.y);
                mma16816(acc[dt][0], acc[dt][1], acc[dt][2], acc[dt][3],
                         phi[0], phi[1], phi[2], phi[3], vf.z, vf.w);
            }
        }
    }

    ls0 += __shfl_xor_sync(0xffffffffu, ls0, 1);
    ls0 += __shfl_xor_sync(0xffffffffu, ls0, 2);
    ls1 += __shfl_xor_sync(0xffffffffu, ls1, 1);
    ls1 += __shfl_xor_sync(0xffffffffu, ls1, 2);

    if (p0 < 100) {
        float* pp = g_part + ((split * 512 + bh) * 100 + p0) * 17;
        pp[c2]     = acc[0][0]; pp[c2 + 1]     = acc[0][1];
        pp[8 + c2] = acc[1][0]; pp[8 + c2 + 1] = acc[1][1];
        if ((lane & 3) == 0) pp[16] = ls0;
    }
    if (p1 < 100) {
        float* pp = g_part + ((split * 512 + bh) * 100 + p1) * 17;
        pp[c2]     = acc[0][2]; pp[c2 + 1]     = acc[0][3];
        pp[8 + c2] = acc[1][2]; pp[8 + c2 + 1] = acc[1][3];
        if ((lane & 3) == 0) pp[16] = ls1;
    }
}

// ============================================================================
// Kernel 4: fused combine (4 splits) + MH = (normalized O) @ Wc + bc
// ============================================================================
__global__ void __launch_bounds__(256)
mh_kernel(const float* __restrict__ Wc, const float* __restrict__ bc) {
    __shared__ float As[128][20];
    __shared__ float sinv[16][8];
    const int tid = threadIdx.x;
    const int R0  = blockIdx.x * 16;
    const int tx  = tid & 63;
    const int ty  = tid >> 6;

    if (tid < 128) {
        int row = tid >> 3, h = tid & 7;
        int gr = R0 + row;
        int b = gr / 100, p = gr % 100;
        int bh = b * 8 + h;
        float ls = 0.f;
        #pragma unroll
        for (int sp = 0; sp < 4; ++sp)
            ls += g_part[((sp * 512 + bh) * 100 + p) * 17 + 16];
        sinv[row][h] = 1.f / ls;
    }
    __syncthreads();

    for (int l = tid; l < 2048; l += 256) {
        int row = l >> 7, col = l & 127;
        int gr = R0 + row;
        int b = gr / 100, p = gr % 100;
        int h = col >> 4, d = col & 15;
        int bh = b * 8 + h;
        float s = 0.f;
        #pragma unroll
        for (int sp = 0; sp < 4; ++sp)
            s += g_part[((sp * 512 + bh) * 100 + p) * 17 + d];
        As[col][row] = s * sinv[row][h];
    }
    __syncthreads();

    u64t acc[4];
    {
        float2 bb = *(const float2*)(bc + tx * 2);
        u64t bb2; asm("mov.b64 %0, {%1, %2};" : "=l"(bb2) : "f"(bb.x), "f"(bb.y));
        acc[0] = bb2; acc[1] = bb2; acc[2] = bb2; acc[3] = bb2;
    }

    #pragma unroll 8
    for (int k = 0; k < 128; ++k) {
        u64t w = *(const u64t*)(Wc + k * 128 + tx * 2);
        float4 a = *(const float4*)&As[k][ty * 4];
        acc[0] = fma2(splat2(a.x), w, acc[0]);
        acc[1] = fma2(splat2(a.y), w, acc[1]);
        acc[2] = fma2(splat2(a.z), w, acc[2]);
        acc[3] = fma2(splat2(a.w), w, acc[3]);
    }

    #pragma unroll
    for (int r = 0; r < 4; ++r)
        *(u64t*)(g_MH + (R0 + ty * 4 + r) * 128 + tx * 2) = acc[r];
}

// ============================================================================
// Kernel 5: score = MH @ E^T via mma.sync with cooperative E fragment
// pre-packing (validated round 14).
// ============================================================================
__global__ void __launch_bounds__(224, 2)
score_kernel(const float* __restrict__ Enodes,
             const float* __restrict__ cur_dist,
             const float* __restrict__ noise,
             float* __restrict__ out) {
    extern __shared__ __align__(16) uint4 EB[];   // [128][33]
    const int tid   = threadIdx.x;
    const int wid   = tid >> 5;
    const int lane  = tid & 31;
    const int rfrag = lane >> 2;
    const int c2    = (lane & 3) * 2;
    const int n0    = blockIdx.x * 128;
    const int b     = blockIdx.y;

    for (int l = tid; l < 4096; l += 224) {
        const int n  = l >> 5;
        const int j  = l & 31;
        const int k  = (j >> 2) * 16 + (j & 3) * 2;
        int gn = n0 + n; if (gn > 999) gn = 999;
        const float* ep = Enodes + (size_t)(b * 1000 + gn) * 128 + k;
        float2 a  = *(const float2*)ep;
        float2 c  = *(const float2*)(ep + 8);
        EB[n * 33 + j] = make_uint4(
            hipack(a.x, a.y), hipack(c.x, c.y),
            packbf2(a.x - hif(a.x), a.y - hif(a.y)),
            packbf2(c.x - hif(c.x), c.y - hif(c.y)));
    }
    __syncthreads();

    const int p0  = wid * 16 + rfrag;
    const int p1  = p0 + 8;
    const int pr0 = p0 < 100 ? p0 : 99;
    const int pr1 = p1 < 100 ? p1 : 99;
    const float* m0base = g_MH + (size_t)(b * 100 + pr0) * 128;
    const float* m1base = g_MH + (size_t)(b * 100 + pr1) * 128;

    float acc[16][4];
    #pragma unroll
    for (int nt = 0; nt < 16; ++nt)
        #pragma unroll
        for (int i = 0; i < 4; ++i) acc[nt][i] = 0.f;

    #pragma unroll
    for (int kk = 0; kk < 8; ++kk) {
        unsigned ahi[4], alo[4];
        {
            float2 x0 = *(const float2*)(m0base + kk * 16 + c2);
            float2 x1 = *(const float2*)(m1base + kk * 16 + c2);
            float2 x2 = *(const float2*)(m0base + kk * 16 + c2 + 8);
            float2 x3 = *(const float2*)(m1base + kk * 16 + c2 + 8);
            ahi[0] = hipack(x0.x, x0.y); ahi[1] = hipack(x1.x, x1.y);
            ahi[2] = hipack(x2.x, x2.y); ahi[3] = hipack(x3.x, x3.y);
            alo[0] = packbf2(x0.x - hif(x0.x), x0.y - hif(x0.y));
            alo[1] = packbf2(x1.x - hif(x1.x), x1.y - hif(x1.y));
            alo[2] = packbf2(x2.x - hif(x2.x), x2.y - hif(x2.y));
            alo[3] = packbf2(x3.x - hif(x3.x), x3.y - hif(x3.y));
        }
        #pragma unroll
        for (int nt = 0; nt < 16; ++nt) {
            uint4 bf = EB[(nt * 8 + rfrag) * 33 + kk * 4 + (lane & 3)];
            mma16816(acc[nt][0], acc[nt][1], acc[nt][2], acc[nt][3],
                     ahi[0], ahi[1], ahi[2], ahi[3], bf.x, bf.y);
            mma16816(acc[nt][0], acc[nt][1], acc[nt][2], acc[nt][3],
                     alo[0], alo[1], alo[2], alo[3], bf.x, bf.y);
            mma16816(acc[nt][0], acc[nt][1], acc[nt][2], acc[nt][3],
                     ahi[0], ahi[1], ahi[2], ahi[3], bf.z, bf.w);
        }
    }

    #pragma unroll
    for (int nt = 0; nt < 16; ++nt) {
        const int cn = n0 + nt * 8 + c2;
        if (cn < 1000) {
            #pragma unroll
            for (int dt = 0; dt < 2; ++dt) {
                const int p = dt ? p1 : p0;
                if (p < 100) {
                    const int idx = (b * 100 + p) * 1000 + cn;
                    float2 cd = *(const float2*)(cur_dist + idx);
                    float2 nz = *(const float2*)(noise + idx);
                    float s0 = acc[nt][dt * 2 + 0];
                    float s1 = acc[nt][dt * 2 + 1];
                    float h0 = -__logf(fmaf(2.f, cd.x, 1e-6f));
                    float h1 = -__logf(fmaf(2.f, cd.y, 1e-6f));
                    float r0 = tanh_scaled(s0 * INV_SQRT_EMB + A_COEF * h0 + B_COEF * nz.x, 10.f);
                    float r1 = tanh_scaled(s1 * INV_SQRT_EMB + A_COEF * h1 + B_COEF * nz.y, 10.f);
                    *(float2*)(out + idx) = make_float2(r0, r1);
                }
            }
        }
    }
}

// ============================================================================
// Kernel 6: masked in-place row softmax, M=10, float4 path; mask from L2.
// ============================================================================
__global__ void __launch_bounds__(256)
softmax_kernel(float* __restrict__ out) {
    const int row = blockIdx.x;
    const int tid = threadIdx.x;
    float* sp = out + row * 1000;

    __shared__ float ssum[8];

    float e0 = 0.f, e1 = 0.f, e2 = 0.f, e3 = 0.f, lsum = 0.f;
    if (tid < 250) {
        float4 v = *(const float4*)(sp + tid * 4);
        const unsigned w  = __ldg(&g_bits[row * 32 + (tid >> 3)]);
        const int      sh = (tid * 4) & 31;
        e0 = ((w >> sh)       & 1u) ? 0.f : __expf(v.x - 10.f);
        e1 = ((w >> (sh + 1)) & 1u) ? 0.f : __expf(v.y - 10.f);
        e2 = ((w >> (sh + 2)) & 1u) ? 0.f : __expf(v.z - 10.f);
        e3 = ((w >> (sh + 3)) & 1u) ? 0.f : __expf(v.w - 10.f);
        lsum = (e0 + e1) + (e2 + e3);
    }
    #pragma unroll
    for (int o = 16; o; o >>= 1) lsum += __shfl_xor_sync(0xffffffffu, lsum, o);
    if ((tid & 31) == 0) ssum[tid >> 5] = lsum;
    __syncthreads();
    float S = 0.f;
    #pragma unroll
    for (int w = 0; w < 8; ++w) S += ssum[w];

    const float inv = 1.f / S;
    if (tid < 250)
        *(float4*)(sp + tid * 4) = make_float4(e0 * inv, e1 * inv, e2 * inv, e3 * inv);
}

// ============================================================================
extern "C" void kernel_launch(void* const* d_in, const int* in_sizes, int n_in,
                              void* d_out, int out_size) {
    const float* eln      = (const float*)d_in[0];
    const float* loadv    = (const float*)d_in[1];
    const float* timev    = (const float*)d_in[2];
    const float* cur_dist = (const float*)d_in[3];
    const float* ninf     = (const float*)d_in[4];
    const float* noise    = (const float*)d_in[5];
    const float* Enodes   = (const float*)d_in[6];
    const float* Wq       = (const float*)d_in[7];
    const float* Wk       = (const float*)d_in[8];
    const float* Wv       = (const float*)d_in[9];
    const float* Wc       = (const float*)d_in[10];
    const float* bc       = (const float*)d_in[11];
    float* out = (float*)d_out;

    const int KV_SMEM = 128 * 132 * 4;   // 67584 B (covers q path's 37888 B)
    const int SC_SMEM = 128 * 33 * 16;   // 67584 B
    cudaFuncSetAttribute(kvq_mma_kernel, cudaFuncAttributeMaxDynamicSharedMemorySize, KV_SMEM);
    cudaFuncSetAttribute(score_kernel,   cudaFuncAttributeMaxDynamicSharedMemorySize, SC_SMEM);

    bits_kernel<<<25600, 256>>>(ninf);
    wprep_kernel<<<50, 256>>>(Wk, Wv, Wq);
    kvq_mma_kernel<<<1100, 256, KV_SMEM>>>(Enodes, eln, loadv, timev);
    attn_kernel<<<dim3(512, 4), 224>>>();
    mh_kernel<<<400, 256>>>(Wc, bc);
    score_kernel<<<dim3(8, 64), 224, SC_SMEM>>>(Enodes, cur_dist, noise, out);
    softmax_kernel<<<6400, 256>>>(out);
}